// round 13
// baseline (speedup 1.0000x reference)
#include <cuda_runtime.h>
#include <cuda_fp16.h>
#include <math.h>

#define NN 50000
#define EE 500000
#define ETOT 550000
#define FEA 16
#define NB 196   // ceil(NN/256)
#define GAT_BLOCKS 1184   // 148 SMs * 8 blocks -> one wave

// ---------------- packed f32x2 helpers (Blackwell dual-lane fp32) ----------------
__device__ __forceinline__ unsigned long long pack2(float x, float y) {
    unsigned long long r;
    asm("mov.b64 %0, {%1, %2};" : "=l"(r) : "f"(x), "f"(y));
    return r;
}
__device__ __forceinline__ void fma2(unsigned long long& d, unsigned long long a,
                                     unsigned long long b) {
    asm("fma.rn.f32x2 %0, %1, %2, %0;" : "+l"(d) : "l"(a), "l"(b));
}
__device__ __forceinline__ float2 unpack2(unsigned long long v) {
    float lo, hi;
    asm("mov.b64 {%0, %1}, %2;" : "=f"(lo), "=f"(hi) : "l"(v));
    return make_float2(lo, hi);
}
__device__ __forceinline__ unsigned bf16pair(float lo, float hi) {
    unsigned r;
    asm("cvt.rn.bf16x2.f32 %0, %1, %2;" : "=r"(r) : "f"(hi), "f"(lo));
    return r;
}

// ---------------- scratch (static device globals; no allocation) ----------------
__device__ float  g_xl1[NN * 256];
__device__ float  g_acc1[NN * 256];
__device__ float  g_xl2[NN * 128];
__device__ float  g_acc2[NN * 128];
__device__ __half g_E1[(EE + 1) * 256];   // edge transform, EID order (+1 self-loop row)
__device__ __half g_E2[(EE + 1) * 128];
__device__ float  g_E3[ETOT];             // CSR order
__device__ float  g_xl3[NN];
__device__ float  g_xr3[NN];
__device__ int    g_cnt[NN];
__device__ int    g_rows[NN + 1];
__device__ int    g_cur[NN];
__device__ int    g_csrc[ETOT];
__device__ int    g_ceid[ETOT];
__device__ int    g_bsums[256];
__device__ int    g_dhist[64];
__device__ int    g_dcur[64];
__device__ int    g_nodeperm[NN];
__device__ double g_sums1[256];
__device__ double g_sumsq1[256];
__device__ double g_sums2[128];
__device__ double g_sumsq2[128];
__device__ double g_easum[FEA];
__device__ float  g_eamean[FEA];

// ---------------- prep: dst histogram + edge_attr column sums (merged) ----------------
#define HIST_BLKS 1954
__global__ void prep_hist_ea_kernel(const int* __restrict__ ei, const float* __restrict__ ea) {
    if (blockIdx.x < HIST_BLKS) {
        int e = blockIdx.x * 256 + threadIdx.x;
        if (e < EE) atomicAdd(&g_cnt[__ldcs(&ei[EE + e])], 1);
    } else {
        long tid = (long)(blockIdx.x - HIST_BLKS) * 256 + threadIdx.x;
        long stride = 512L * 256;
        int k = (int)(tid & 15);
        double sv = 0.0;
        for (long i = tid; i < (long)EE * FEA; i += stride) sv += (double)__ldcs(&ea[i]);
        atomicAdd(&g_easum[k], sv);
    }
}

// ---------------- CSR scan chain (+ degree histogram for node sort) ----------------
__global__ void scan1_kernel() {
    __shared__ int s[256];
    int t = threadIdx.x;
    int i = blockIdx.x * 256 + t;
    int v = 0;
    if (i < NN) {
        v = g_cnt[i] + 1;   // +1 self loop
        g_cnt[i] = v;
        atomicAdd(&g_dhist[min(v, 63)], 1);
    }
    s[t] = v;
    __syncthreads();
#pragma unroll
    for (int off = 1; off < 256; off <<= 1) {
        int x = (t >= off) ? s[t - off] : 0;
        __syncthreads();
        s[t] += x;
        __syncthreads();
    }
    if (i < NN) g_rows[i] = s[t];
    if (t == 255) g_bsums[blockIdx.x] = s[255];
}
__global__ void scan2_kernel() {
    __shared__ int s[256];
    int t = threadIdx.x;
    if (t < FEA) {
        g_eamean[t] = (float)(g_easum[t] / (double)EE);
        g_easum[t] = 0.0;
    }
    g_sums1[t] = 0.0; g_sumsq1[t] = 0.0;
    if (t < 128) { g_sums2[t] = 0.0; g_sumsq2[t] = 0.0; }
    int v = (t < NB) ? g_bsums[t] : 0;
    s[t] = v;
    __syncthreads();
#pragma unroll
    for (int off = 1; off < 256; off <<= 1) {
        int x = (t >= off) ? s[t - off] : 0;
        __syncthreads();
        s[t] += x;
        __syncthreads();
    }
    g_bsums[t] = s[t] - v;
    __syncthreads();
    int dv = (t < 64) ? g_dhist[t] : 0;
    s[t] = dv;
    __syncthreads();
#pragma unroll
    for (int off = 1; off < 64; off <<= 1) {
        int x = (t >= off) ? s[t - off] : 0;
        __syncthreads();
        s[t] += x;
        __syncthreads();
    }
    if (t < 64) g_dcur[t] = NN - s[t];
}
__global__ void scan3_kernel() {
    int i = blockIdx.x * blockDim.x + threadIdx.x;
    if (i < NN) {
        int deg = g_cnt[i];
        int r = g_rows[i] - deg + g_bsums[i >> 8];
        g_rows[i] = r;
        g_cur[i] = r;
        int pos = atomicAdd(&g_dcur[min(deg, 63)], 1);
        g_nodeperm[pos] = i;
    }
    if (i == 0) g_rows[NN] = ETOT;
}
// CSR scatter + E3 + self-loop rows of E1/E2; resets g_cnt/g_dhist
__global__ void csr_scatter_kernel(const int* __restrict__ ei, const float* __restrict__ ea,
                                   const float* __restrict__ We3,
                                   const float* __restrict__ We1, const float* __restrict__ We2,
                                   __half* __restrict__ E1, __half* __restrict__ E2) {
    __shared__ float We_s[FEA];
    __shared__ float mean_s[FEA];
    __shared__ float mdot;
    if (threadIdx.x < FEA) {
        We_s[threadIdx.x] = We3[threadIdx.x];
        mean_s[threadIdx.x] = g_eamean[threadIdx.x];
    }
    __syncthreads();
    if (threadIdx.x == 0) {
        float s = 0.f;
#pragma unroll
        for (int k = 0; k < FEA; k++) s += mean_s[k] * We_s[k];
        mdot = s;
    }
    __syncthreads();
    if (blockIdx.x == 0) {
        int c = threadIdx.x;
        {
            float s = 0.f;
#pragma unroll
            for (int k = 0; k < FEA; k++) s += mean_s[k] * We1[k * 256 + c];
            E1[(size_t)EE * 256 + c] = __float2half_rn(s);
        }
        if (c < 128) {
            float s = 0.f;
#pragma unroll
            for (int k = 0; k < FEA; k++) s += mean_s[k] * We2[k * 128 + c];
            E2[(size_t)EE * 128 + c] = __float2half_rn(s);
        }
    }
    int e = blockIdx.x * blockDim.x + threadIdx.x;
    if (e >= ETOT) return;
    if (e < NN) g_cnt[e] = 0;
    if (e < 64) g_dhist[e] = 0;
    int s, d, eid;
    float dot;
    if (e < EE) {
        s = ei[e]; d = ei[EE + e]; eid = e;
        dot = 0.f;
        const float* eap = ea + (size_t)e * FEA;
#pragma unroll
        for (int k = 0; k < FEA; k++) dot += __ldcs(&eap[k]) * We_s[k];
    } else {
        s = e - EE; d = s; eid = EE;
        dot = mdot;
    }
    int pos = atomicAdd(&g_cur[d], 1);
    g_csrc[pos] = s;
    g_ceid[pos] = eid;
    g_E3[pos] = dot;
}

// ---------------- tensor-core egemm: E1|E2 = ea @ [We1|We2], bf16 mma, fp16 out --------
// Block: 128 edges. 8 warps x 6 strided 8-col groups cover 384 output cols.
// mma.sync.m16n8k16 row.col f32.bf16.bf16.f32.
__global__ void __launch_bounds__(256)
egemm_mma_kernel(const float* __restrict__ ea,
                 const float* __restrict__ We1, const float* __restrict__ We2,
                 __half* __restrict__ E1, __half* __restrict__ E2) {
    __shared__ unsigned short sA[128 * 16];    // [edge][k] bf16
    __shared__ unsigned short sBt[384 * 16];   // [col][k]  bf16 (transposed)
    int tid = threadIdx.x;
    int warp = tid >> 5, lane = tid & 31;
    int g = lane >> 2, tg = lane & 3;
    int e0 = blockIdx.x * 128;

    // load A: thread -> (row = tid>>1, half-row q = tid&1), convert 8 floats to bf16
    {
        int row = tid >> 1, q = tid & 1;
        int e = e0 + row;
        unsigned u[4];
        if (e < EE) {
            const float4* p = reinterpret_cast<const float4*>(ea + (size_t)e * 16 + q * 8);
            float4 v0 = __ldcs(&p[0]);
            float4 v1 = __ldcs(&p[1]);
            u[0] = bf16pair(v0.x, v0.y);
            u[1] = bf16pair(v0.z, v0.w);
            u[2] = bf16pair(v1.x, v1.y);
            u[3] = bf16pair(v1.z, v1.w);
        } else u[0] = u[1] = u[2] = u[3] = 0u;
        *reinterpret_cast<uint4*>(&sA[row * 16 + q * 8]) =
            make_uint4(u[0], u[1], u[2], u[3]);
    }
    // load B transposed: sBt[c][k] for c in [0,384)
    for (int idx = tid; idx < 384 * 16; idx += 256) {
        int c = idx >> 4, k = idx & 15;
        float v = (c < 256) ? We1[k * 256 + c] : We2[k * 128 + (c - 256)];
        sBt[c * 16 + k] = (unsigned short)(bf16pair(v, 0.f) & 0xffffu);
    }
    __syncthreads();

    // preload 6 B fragments (groups n = warp + j*8, colbase = n*8)
    unsigned bf0[6], bf1[6];
    const __half* dstBase[6];
    int dstD[6], dstC[6];
#pragma unroll
    for (int j = 0; j < 6; j++) {
        int cb = (warp + j * 8) * 8;
        int col = cb + g;
        bf0[j] = *reinterpret_cast<const unsigned*>(&sBt[col * 16 + 2 * tg]);
        bf1[j] = *reinterpret_cast<const unsigned*>(&sBt[col * 16 + 2 * tg + 8]);
        if (cb < 256) { dstBase[j] = E1; dstD[j] = 256; dstC[j] = cb; }
        else          { dstBase[j] = E2; dstD[j] = 128; dstC[j] = cb - 256; }
    }

#pragma unroll
    for (int eg = 0; eg < 8; eg++) {
        int r0 = eg * 16 + g;
        unsigned a0 = *reinterpret_cast<const unsigned*>(&sA[r0 * 16 + 2 * tg]);
        unsigned a1 = *reinterpret_cast<const unsigned*>(&sA[(r0 + 8) * 16 + 2 * tg]);
        unsigned a2 = *reinterpret_cast<const unsigned*>(&sA[r0 * 16 + 2 * tg + 8]);
        unsigned a3 = *reinterpret_cast<const unsigned*>(&sA[(r0 + 8) * 16 + 2 * tg + 8]);
        int ge0 = e0 + r0;        // global edge for rows g / g+8
        bool w0 = ge0 < EE, w1 = (ge0 + 8) < EE;
#pragma unroll
        for (int j = 0; j < 6; j++) {
            float c0, c1, c2, c3;
            asm volatile(
                "mma.sync.aligned.m16n8k16.row.col.f32.bf16.bf16.f32 "
                "{%0,%1,%2,%3}, {%4,%5,%6,%7}, {%8,%9}, {%10,%11,%12,%13};"
                : "=f"(c0), "=f"(c1), "=f"(c2), "=f"(c3)
                : "r"(a0), "r"(a1), "r"(a2), "r"(a3), "r"(bf0[j]), "r"(bf1[j]),
                  "f"(0.f), "f"(0.f), "f"(0.f), "f"(0.f));
            __half2 h01 = __floats2half2_rn(c0, c1);
            __half2 h23 = __floats2half2_rn(c2, c3);
            if (w0)
                __stcs(reinterpret_cast<unsigned*>(
                           const_cast<__half*>(dstBase[j]) + (size_t)ge0 * dstD[j] + dstC[j] + 2 * tg),
                       *reinterpret_cast<unsigned*>(&h01));
            if (w1)
                __stcs(reinterpret_cast<unsigned*>(
                           const_cast<__half*>(dstBase[j]) + (size_t)(ge0 + 8) * dstD[j] + dstC[j] + 2 * tg),
                       *reinterpret_cast<unsigned*>(&h23));
        }
    }
}

// ---------------- SGEMM 128x128 tile, 8x8/thread, f32x2 packed, double-buffered ----------------
template <int K, int M, bool FUSE_BN>
__global__ void __launch_bounds__(256, 2)
gemm_bias_v3(const float* __restrict__ A, const float* __restrict__ B,
             const float* __restrict__ bias, float* __restrict__ C, int n,
             const float* __restrict__ gam, const float* __restrict__ bet) {
    __shared__ float As[2][16][132];
    __shared__ float Bs[2][16][132];
    __shared__ float sSc[FUSE_BN ? K : 1];
    __shared__ float sSh[FUSE_BN ? K : 1];
    constexpr int KT = K / 16;
    int tid = threadIdx.x;
    int tx = tid & 15, ty = tid >> 4;
    int row0 = blockIdx.y * 128, col0 = blockIdx.x * 128;

    if (FUSE_BN) {
        for (int j = tid; j < K; j += 256) {
            double mu = g_sums1[j] / (double)NN;
            double var = g_sumsq1[j] / (double)NN - mu * mu;
            float sc = gam[j] * rsqrtf((float)var + 1e-5f);
            sSc[j] = sc;
            sSh[j] = bet[j] - sc * (float)mu;
        }
        __syncthreads();
    }

    int a_r = tid >> 2, a_q = tid & 3;
    int b_kr = tid >> 5, b_cq = tid & 31;

    float4 aR[2], bR[2];
    auto bnf = [&](float a, int k) -> float {
        if (!FUSE_BN) return a;
        float y = sSc[k] * a + sSh[k];
        return y > 0.f ? y : (__expf(y) - 1.f);
    };
    auto loadG = [&](int kk) {
#pragma unroll
        for (int u = 0; u < 2; u++) {
            int grow = row0 + a_r + u * 64;
            aR[u] = (grow < n) ? reinterpret_cast<const float4*>(A + (size_t)grow * K + kk)[a_q]
                               : make_float4(0.f, 0.f, 0.f, 0.f);
            bR[u] = reinterpret_cast<const float4*>(B + (size_t)(kk + b_kr + u * 8) * M + col0)[b_cq];
        }
    };
    auto storeS = [&](int buf, int kk) {
#pragma unroll
        for (int u = 0; u < 2; u++) {
            int r = a_r + u * 64;
            As[buf][a_q * 4 + 0][r] = bnf(aR[u].x, kk + a_q * 4 + 0);
            As[buf][a_q * 4 + 1][r] = bnf(aR[u].y, kk + a_q * 4 + 1);
            As[buf][a_q * 4 + 2][r] = bnf(aR[u].z, kk + a_q * 4 + 2);
            As[buf][a_q * 4 + 3][r] = bnf(aR[u].w, kk + a_q * 4 + 3);
            reinterpret_cast<float4*>(&Bs[buf][b_kr + u * 8][0])[b_cq] = bR[u];
        }
    };

    unsigned long long acc[8][4];
#pragma unroll
    for (int i = 0; i < 8; i++)
#pragma unroll
        for (int j = 0; j < 4; j++) acc[i][j] = pack2(0.f, 0.f);

    loadG(0);
    storeS(0, 0);
    __syncthreads();
#pragma unroll
    for (int kt = 0; kt < KT; kt++) {
        if (kt + 1 < KT) loadG((kt + 1) * 16);
        int cur = kt & 1;
#pragma unroll
        for (int k = 0; k < 16; k++) {
            float a[8];
            float4 b4[2];
            *reinterpret_cast<float4*>(a)     = *reinterpret_cast<const float4*>(&As[cur][k][ty * 8]);
            *reinterpret_cast<float4*>(a + 4) = *reinterpret_cast<const float4*>(&As[cur][k][ty * 8 + 4]);
            b4[0] = *reinterpret_cast<const float4*>(&Bs[cur][k][tx * 8]);
            b4[1] = *reinterpret_cast<const float4*>(&Bs[cur][k][tx * 8 + 4]);
            const unsigned long long* bv = reinterpret_cast<const unsigned long long*>(b4);
#pragma unroll
            for (int i = 0; i < 8; i++) {
                unsigned long long av = pack2(a[i], a[i]);
#pragma unroll
                for (int j = 0; j < 4; j++) fma2(acc[i][j], av, bv[j]);
            }
        }
        if (kt + 1 < KT) {
            storeS((kt + 1) & 1, (kt + 1) * 16);
            __syncthreads();
        }
    }
    float4 bv0 = reinterpret_cast<const float4*>(bias + col0 + tx * 8)[0];
    float4 bv1 = reinterpret_cast<const float4*>(bias + col0 + tx * 8)[1];
    float bb[8] = {bv0.x, bv0.y, bv0.z, bv0.w, bv1.x, bv1.y, bv1.z, bv1.w};
#pragma unroll
    for (int i = 0; i < 8; i++) {
        int r = row0 + ty * 8 + i;
        if (r < n) {
            float w[8];
#pragma unroll
            for (int j = 0; j < 4; j++) {
                float2 p = unpack2(acc[i][j]);
                w[j * 2] = p.x + bb[j * 2];
                w[j * 2 + 1] = p.y + bb[j * 2 + 1];
            }
            float4* cp = reinterpret_cast<float4*>(C + (size_t)r * M + col0 + tx * 8);
            cp[0] = make_float4(w[0], w[1], w[2], w[3]);
            cp[1] = make_float4(w[4], w[5], w[6], w[7]);
        }
    }
}

// ---------------- warp-persistent GATv2 attention + register BN accumulation ----------
template <int D>
__global__ void __launch_bounds__(256)
gat_node_kernel(const float* __restrict__ xl, const __half* __restrict__ E,
                const float* __restrict__ att, float* __restrict__ outx,
                double* __restrict__ sums, double* __restrict__ sumsq) {
    constexpr int CPL = D / 32;
    constexpr int NC4 = CPL / 4;
    __shared__ float bsum[8][D];
    __shared__ float bsq[8][D];
    int w = threadIdx.x >> 5;
    int lane = threadIdx.x & 31;

    const float4* at4 = reinterpret_cast<const float4*>(att);
    float4 attv[NC4];
    float fsum[CPL], fsq[CPL];
#pragma unroll
    for (int v = 0; v < NC4; v++) attv[v] = at4[lane * NC4 + v];
#pragma unroll
    for (int c = 0; c < CPL; c++) { fsum[c] = 0.f; fsq[c] = 0.f; }

    auto load_er = [&](int eid, uint4& er) {
        if (NC4 == 2) {
            er = __ldcs(reinterpret_cast<const uint4*>(E + (size_t)eid * D) + lane);
        } else {
            uint2 t = __ldcs(reinterpret_cast<const uint2*>(E + (size_t)eid * D) + lane);
            er.x = t.x; er.y = t.y; er.z = 0u; er.w = 0u;
        }
    };

    for (int g = blockIdx.x * 8 + w; g < NN; g += GAT_BLOCKS * 8) {
        int node = g_nodeperm[g];
        int beg = g_rows[node], end = g_rows[node + 1];
        const float4* xd4 = reinterpret_cast<const float4*>(xl + (size_t)node * D);
        float4 xdv[NC4], accv[NC4];
        float den = 0.f;
#pragma unroll
        for (int v = 0; v < NC4; v++) {
            xdv[v] = xd4[lane * NC4 + v];
            accv[v] = make_float4(0.f, 0.f, 0.f, 0.f);
        }

        auto edge_compute = [&](const float4 (&xs)[NC4], const uint4& er) {
            float p = 0.f;
#pragma unroll
            for (int v = 0; v < NC4; v++) {
                unsigned w0 = (v == 0) ? er.x : er.z;
                unsigned w1 = (v == 0) ? er.y : er.w;
                float2 e01 = __half22float2(*reinterpret_cast<const __half2*>(&w0));
                float2 e23 = __half22float2(*reinterpret_cast<const __half2*>(&w1));
                float m0 = xs[v].x + xdv[v].x + e01.x;
                float m1 = xs[v].y + xdv[v].y + e01.y;
                float m2 = xs[v].z + xdv[v].z + e23.x;
                float m3 = xs[v].w + xdv[v].w + e23.y;
                float l0 = m0 > 0.f ? m0 : 0.2f * m0;
                float l1 = m1 > 0.f ? m1 : 0.2f * m1;
                float l2 = m2 > 0.f ? m2 : 0.2f * m2;
                float l3 = m3 > 0.f ? m3 : 0.2f * m3;
                p += l0 * attv[v].x + l1 * attv[v].y + l2 * attv[v].z + l3 * attv[v].w;
            }
            p += __shfl_xor_sync(0xffffffffu, p, 1);
            p += __shfl_xor_sync(0xffffffffu, p, 2);
            float ev = __expf(p);
            den += ev;
#pragma unroll
            for (int v = 0; v < NC4; v++) {
                accv[v].x += ev * xs[v].x;
                accv[v].y += ev * xs[v].y;
                accv[v].z += ev * xs[v].z;
                accv[v].w += ev * xs[v].w;
            }
        };

        int i = beg;
        for (; i + 4 <= end; i += 4) {
            int s0 = g_csrc[i], s1 = g_csrc[i + 1], s2 = g_csrc[i + 2], s3 = g_csrc[i + 3];
            int e0 = g_ceid[i], e1 = g_ceid[i + 1], e2 = g_ceid[i + 2], e3 = g_ceid[i + 3];
            float4 xs0[NC4], xs1[NC4], xs2[NC4], xs3[NC4];
            uint4 er0, er1, er2, er3;
            const float4* a0 = reinterpret_cast<const float4*>(xl + (size_t)s0 * D);
            const float4* a1 = reinterpret_cast<const float4*>(xl + (size_t)s1 * D);
            const float4* a2 = reinterpret_cast<const float4*>(xl + (size_t)s2 * D);
            const float4* a3 = reinterpret_cast<const float4*>(xl + (size_t)s3 * D);
#pragma unroll
            for (int v = 0; v < NC4; v++) {
                xs0[v] = a0[lane * NC4 + v];
                xs1[v] = a1[lane * NC4 + v];
                xs2[v] = a2[lane * NC4 + v];
                xs3[v] = a3[lane * NC4 + v];
            }
            load_er(e0, er0); load_er(e1, er1); load_er(e2, er2); load_er(e3, er3);
            edge_compute(xs0, er0);
            edge_compute(xs1, er1);
            edge_compute(xs2, er2);
            edge_compute(xs3, er3);
        }
        for (; i < end; i++) {
            int s0 = g_csrc[i];
            int e0 = g_ceid[i];
            float4 xs0[NC4];
            uint4 er0;
            const float4* a0 = reinterpret_cast<const float4*>(xl + (size_t)s0 * D);
#pragma unroll
            for (int v = 0; v < NC4; v++) xs0[v] = a0[lane * NC4 + v];
            load_er(e0, er0);
            edge_compute(xs0, er0);
        }

        float4* o4 = reinterpret_cast<float4*>(outx + (size_t)node * D);
        float inv = 1.f / (den + 1e-16f);
#pragma unroll
        for (int v = 0; v < NC4; v++) {
            float4 o = make_float4(accv[v].x * inv, accv[v].y * inv,
                                   accv[v].z * inv, accv[v].w * inv);
            o4[lane * NC4 + v] = o;
            fsum[v * 4 + 0] += o.x; fsq[v * 4 + 0] += o.x * o.x;
            fsum[v * 4 + 1] += o.y; fsq[v * 4 + 1] += o.y * o.y;
            fsum[v * 4 + 2] += o.z; fsq[v * 4 + 2] += o.z * o.z;
            fsum[v * 4 + 3] += o.w; fsq[v * 4 + 3] += o.w * o.w;
        }
    }

#pragma unroll
    for (int c = 0; c < CPL; c++) {
        bsum[w][lane * CPL + c] = fsum[c];
        bsq[w][lane * CPL + c] = fsq[c];
    }
    __syncthreads();
    int c = threadIdx.x;
    if (c < D) {
        float s = 0.f, s2 = 0.f;
#pragma unroll
        for (int u = 0; u < 8; u++) { s += bsum[u][c]; s2 += bsq[u][c]; }
        atomicAdd(&sums[c], (double)s);
        atomicAdd(&sumsq[c], (double)s2);
    }
}

// ---------------- layer 3: BN+ELU fused into the two scalar transforms ----------------
__global__ void lin3_kernel(const float* __restrict__ h2,
                            const float* __restrict__ gam, const float* __restrict__ bet,
                            const float* __restrict__ W3l, const float* __restrict__ b3l,
                            const float* __restrict__ W3r, const float* __restrict__ b3r) {
    __shared__ float sSc[128], sSh[128];
    int tid = threadIdx.x;
    if (tid < 128) {
        double mu = g_sums2[tid] / (double)NN;
        double var = g_sumsq2[tid] / (double)NN - mu * mu;
        float sc = gam[tid] * rsqrtf((float)var + 1e-5f);
        sSc[tid] = sc;
        sSh[tid] = bet[tid] - sc * (float)mu;
    }
    __syncthreads();
    int w = blockIdx.x * 8 + (tid >> 5);
    if (w >= NN) return;
    int lane = tid & 31;
    const float* row = h2 + (size_t)w * 128;
    float sl = 0.f, sr = 0.f;
#pragma unroll
    for (int q = 0; q < 4; q++) {
        int j = q * 32 + lane;
        float v = sSc[j] * row[j] + sSh[j];
        v = v > 0.f ? v : (__expf(v) - 1.f);
        sl += v * W3l[j];
        sr += v * W3r[j];
    }
#pragma unroll
    for (int off = 16; off >= 1; off >>= 1) {
        sl += __shfl_down_sync(0xffffffffu, sl, off);
        sr += __shfl_down_sync(0xffffffffu, sr, off);
    }
    if (lane == 0) {
        g_xl3[w] = sl + b3l[0];
        g_xr3[w] = sr + b3r[0];
    }
}

__global__ void gat3_kernel(float* __restrict__ out, const float* __restrict__ att3,
                            const float* __restrict__ bo3) {
    int node = blockIdx.x * 8 + (threadIdx.x >> 5);
    if (node >= NN) return;
    int lane = threadIdx.x & 31;
    int beg = g_rows[node], end = g_rows[node + 1];
    float xr = g_xr3[node];
    float a3 = att3[0];
    float num = 0.f, den = 0.f;
    for (int i = beg + lane; i < end; i += 32) {
        int s = g_csrc[i];
        float xls = g_xl3[s];
        float m = xls + xr + g_E3[i];
        float lg = (m > 0.f ? m : 0.2f * m) * a3;
        float ev = __expf(lg);
        den += ev;
        num += ev * xls;
    }
#pragma unroll
    for (int off = 16; off >= 1; off >>= 1) {
        num += __shfl_down_sync(0xffffffffu, num, off);
        den += __shfl_down_sync(0xffffffffu, den, off);
    }
    if (lane == 0) out[node] = num / (den + 1e-16f) + bo3[0];
}

// ---------------- host launch ----------------
extern "C" void kernel_launch(void* const* d_in, const int* in_sizes, int n_in,
                              void* d_out, int out_size) {
    const float* x    = (const float*)d_in[0];
    const int*   ei   = (const int*)d_in[1];
    const float* ea   = (const float*)d_in[2];
    const float* W1   = (const float*)d_in[3];
    const float* b1   = (const float*)d_in[4];
    const float* We1  = (const float*)d_in[5];
    const float* att1 = (const float*)d_in[6];
    // d_in[7] = bo1: cancels in BatchNorm
    const float* g1   = (const float*)d_in[8];
    const float* bt1  = (const float*)d_in[9];
    const float* W2   = (const float*)d_in[10];
    const float* b2   = (const float*)d_in[11];
    const float* We2  = (const float*)d_in[12];
    const float* att2 = (const float*)d_in[13];
    // d_in[14] = bo2: cancels in BatchNorm
    const float* g2   = (const float*)d_in[15];
    const float* bt2  = (const float*)d_in[16];
    const float* W3l  = (const float*)d_in[17];
    const float* b3l  = (const float*)d_in[18];
    const float* W3r  = (const float*)d_in[19];
    const float* b3r  = (const float*)d_in[20];
    const float* We3  = (const float*)d_in[21];
    const float* att3 = (const float*)d_in[22];
    const float* bo3  = (const float*)d_in[23];
    float* out = (float*)d_out;

    float *xl1, *acc1, *xl2, *acc2;
    __half *E1, *E2;
    double *sums1, *sumsq1, *sums2, *sumsq2;
    cudaGetSymbolAddress((void**)&xl1,  g_xl1);
    cudaGetSymbolAddress((void**)&acc1, g_acc1);
    cudaGetSymbolAddress((void**)&xl2,  g_xl2);
    cudaGetSymbolAddress((void**)&acc2, g_acc2);
    cudaGetSymbolAddress((void**)&E1,   g_E1);
    cudaGetSymbolAddress((void**)&E2,   g_E2);
    cudaGetSymbolAddress((void**)&sums1, g_sums1);
    cudaGetSymbolAddress((void**)&sumsq1, g_sumsq1);
    cudaGetSymbolAddress((void**)&sums2, g_sums2);
    cudaGetSymbolAddress((void**)&sumsq2, g_sumsq2);

    static cudaStream_t sB = nullptr, sC = nullptr;
    static cudaEvent_t evFork = nullptr, evG1 = nullptr, evEg = nullptr;
    if (sB == nullptr) {
        cudaStreamCreateWithFlags(&sB, cudaStreamNonBlocking);
        cudaStreamCreateWithFlags(&sC, cudaStreamNonBlocking);
        cudaEventCreateWithFlags(&evFork, cudaEventDisableTiming);
        cudaEventCreateWithFlags(&evG1, cudaEventDisableTiming);
        cudaEventCreateWithFlags(&evEg, cudaEventDisableTiming);
    }

    // fork: gemm1 (sB) and the tensor-core egemm (sC) overlap prep (main)
    cudaEventRecord(evFork, 0);
    cudaStreamWaitEvent(sB, evFork, 0);
    cudaStreamWaitEvent(sC, evFork, 0);

    prep_hist_ea_kernel<<<HIST_BLKS + 512, 256>>>(ei, ea);                         // launch 1
    gemm_bias_v3<128, 256, false><<<dim3(2, (NN + 127) / 128), 256, 0, sB>>>(
        x, W1, b1, xl1, NN, nullptr, nullptr);                                     // launch 2
    cudaEventRecord(evG1, sB);
    scan1_kernel<<<NB, 256>>>();                                                   // launch 3
    egemm_mma_kernel<<<(EE + 127) / 128, 256, 0, sC>>>(ea, We1, We2, E1, E2);      // launch 4 <- profiled
    cudaEventRecord(evEg, sC);

    scan2_kernel<<<1, 256>>>();                                                    // launch 5
    scan3_kernel<<<NB, 256>>>();                                                   // launch 6
    csr_scatter_kernel<<<(ETOT + 255) / 256, 256>>>(ei, ea, We3, We1, We2, E1, E2);// launch 7

    // layer 1 attention: needs xl1 (sB) + E1 (sC) + CSR (main)
    cudaStreamWaitEvent(0, evG1, 0);
    cudaStreamWaitEvent(0, evEg, 0);
    gat_node_kernel<256><<<GAT_BLOCKS, 256>>>(xl1, E1, att1, acc1, sums1, sumsq1); // launch 8

    // layer 2
    gemm_bias_v3<256, 128, true><<<dim3(1, (NN + 127) / 128), 256>>>(
        acc1, W2, b2, xl2, NN, g1, bt1);                                           // launch 9
    gat_node_kernel<128><<<GAT_BLOCKS, 256>>>(xl2, E2, att2, acc2, sums2, sumsq2); // launch 10

    // layer 3
    lin3_kernel<<<(NN + 7) / 8, 256>>>(acc2, g2, bt2, W3l, b3l, W3r, b3r);         // launch 11
    gat3_kernel<<<(NN + 7) / 8, 256>>>(out, att3, bo3);                            // launch 12
}

// round 14
// speedup vs baseline: 1.0370x; 1.0370x over previous
#include <cuda_runtime.h>
#include <cuda_fp16.h>
#include <math.h>

#define NN 50000
#define EE 500000
#define ETOT 550000
#define FEA 16
#define NB 196   // ceil(NN/256)
#define GAT_BLOCKS 1184   // 148 SMs * 8 blocks -> one wave

// ---------------- packed f32x2 helpers (Blackwell dual-lane fp32) ----------------
__device__ __forceinline__ unsigned long long pack2(float x, float y) {
    unsigned long long r;
    asm("mov.b64 %0, {%1, %2};" : "=l"(r) : "f"(x), "f"(y));
    return r;
}
__device__ __forceinline__ void fma2(unsigned long long& d, unsigned long long a,
                                     unsigned long long b) {
    asm("fma.rn.f32x2 %0, %1, %2, %0;" : "+l"(d) : "l"(a), "l"(b));
}
__device__ __forceinline__ float2 unpack2(unsigned long long v) {
    float lo, hi;
    asm("mov.b64 {%0, %1}, %2;" : "=f"(lo), "=f"(hi) : "l"(v));
    return make_float2(lo, hi);
}
__device__ __forceinline__ unsigned to_tf32(float v) {
    unsigned r;
    asm("cvt.rna.tf32.f32 %0, %1;" : "=r"(r) : "f"(v));
    return r;
}

// ---------------- scratch (static device globals; no allocation) ----------------
__device__ float  g_xl1[NN * 256];
__device__ float  g_acc1[NN * 256];
__device__ float  g_xl2[NN * 128];
__device__ float  g_acc2[NN * 128];
__device__ __half g_E1[(EE + 1) * 256];   // edge transform, EID order (+1 self-loop row)
__device__ __half g_E2[(EE + 1) * 128];
__device__ float  g_E3[ETOT];             // CSR order
__device__ float  g_xl3[NN];
__device__ float  g_xr3[NN];
__device__ int    g_cnt[NN];
__device__ int    g_rows[NN + 1];
__device__ int    g_cur[NN];
__device__ int    g_csrc[ETOT];
__device__ int    g_ceid[ETOT];
__device__ int    g_bsums[256];
__device__ int    g_dhist[64];
__device__ int    g_dcur[64];
__device__ int    g_nodeperm[NN];
__device__ double g_sums1[256];
__device__ double g_sumsq1[256];
__device__ double g_sums2[128];
__device__ double g_sumsq2[128];
__device__ double g_easum[FEA];
__device__ float  g_eamean[FEA];

// ---------------- prep: dst histogram + edge_attr column sums (merged) ----------------
#define HIST_BLKS 1954
__global__ void prep_hist_ea_kernel(const int* __restrict__ ei, const float* __restrict__ ea) {
    if (blockIdx.x < HIST_BLKS) {
        int e = blockIdx.x * 256 + threadIdx.x;
        if (e < EE) atomicAdd(&g_cnt[__ldcs(&ei[EE + e])], 1);
    } else {
        long tid = (long)(blockIdx.x - HIST_BLKS) * 256 + threadIdx.x;
        long stride = 512L * 256;
        int k = (int)(tid & 15);
        double sv = 0.0;
        for (long i = tid; i < (long)EE * FEA; i += stride) sv += (double)__ldcs(&ea[i]);
        atomicAdd(&g_easum[k], sv);
    }
}

// ---------------- CSR scan chain (+ degree histogram for node sort) ----------------
__global__ void scan1_kernel() {
    __shared__ int s[256];
    int t = threadIdx.x;
    int i = blockIdx.x * 256 + t;
    int v = 0;
    if (i < NN) {
        v = g_cnt[i] + 1;   // +1 self loop
        g_cnt[i] = v;
        atomicAdd(&g_dhist[min(v, 63)], 1);
    }
    s[t] = v;
    __syncthreads();
#pragma unroll
    for (int off = 1; off < 256; off <<= 1) {
        int x = (t >= off) ? s[t - off] : 0;
        __syncthreads();
        s[t] += x;
        __syncthreads();
    }
    if (i < NN) g_rows[i] = s[t];
    if (t == 255) g_bsums[blockIdx.x] = s[255];
}
__global__ void scan2_kernel() {
    __shared__ int s[256];
    int t = threadIdx.x;
    if (t < FEA) {
        g_eamean[t] = (float)(g_easum[t] / (double)EE);
        g_easum[t] = 0.0;
    }
    g_sums1[t] = 0.0; g_sumsq1[t] = 0.0;
    if (t < 128) { g_sums2[t] = 0.0; g_sumsq2[t] = 0.0; }
    int v = (t < NB) ? g_bsums[t] : 0;
    s[t] = v;
    __syncthreads();
#pragma unroll
    for (int off = 1; off < 256; off <<= 1) {
        int x = (t >= off) ? s[t - off] : 0;
        __syncthreads();
        s[t] += x;
        __syncthreads();
    }
    g_bsums[t] = s[t] - v;
    __syncthreads();
    int dv = (t < 64) ? g_dhist[t] : 0;
    s[t] = dv;
    __syncthreads();
#pragma unroll
    for (int off = 1; off < 64; off <<= 1) {
        int x = (t >= off) ? s[t - off] : 0;
        __syncthreads();
        s[t] += x;
        __syncthreads();
    }
    if (t < 64) g_dcur[t] = NN - s[t];
}
__global__ void scan3_kernel() {
    int i = blockIdx.x * blockDim.x + threadIdx.x;
    if (i < NN) {
        int deg = g_cnt[i];
        int r = g_rows[i] - deg + g_bsums[i >> 8];
        g_rows[i] = r;
        g_cur[i] = r;
        int pos = atomicAdd(&g_dcur[min(deg, 63)], 1);
        g_nodeperm[pos] = i;
    }
    if (i == 0) g_rows[NN] = ETOT;
}
// CSR scatter + E3 + self-loop rows of E1/E2; resets g_cnt/g_dhist
__global__ void csr_scatter_kernel(const int* __restrict__ ei, const float* __restrict__ ea,
                                   const float* __restrict__ We3,
                                   const float* __restrict__ We1, const float* __restrict__ We2,
                                   __half* __restrict__ E1, __half* __restrict__ E2) {
    __shared__ float We_s[FEA];
    __shared__ float mean_s[FEA];
    __shared__ float mdot;
    if (threadIdx.x < FEA) {
        We_s[threadIdx.x] = We3[threadIdx.x];
        mean_s[threadIdx.x] = g_eamean[threadIdx.x];
    }
    __syncthreads();
    if (threadIdx.x == 0) {
        float s = 0.f;
#pragma unroll
        for (int k = 0; k < FEA; k++) s += mean_s[k] * We_s[k];
        mdot = s;
    }
    __syncthreads();
    if (blockIdx.x == 0) {
        int c = threadIdx.x;
        {
            float s = 0.f;
#pragma unroll
            for (int k = 0; k < FEA; k++) s += mean_s[k] * We1[k * 256 + c];
            E1[(size_t)EE * 256 + c] = __float2half_rn(s);
        }
        if (c < 128) {
            float s = 0.f;
#pragma unroll
            for (int k = 0; k < FEA; k++) s += mean_s[k] * We2[k * 128 + c];
            E2[(size_t)EE * 128 + c] = __float2half_rn(s);
        }
    }
    int e = blockIdx.x * blockDim.x + threadIdx.x;
    if (e >= ETOT) return;
    if (e < NN) g_cnt[e] = 0;
    if (e < 64) g_dhist[e] = 0;
    int s, d, eid;
    float dot;
    if (e < EE) {
        s = ei[e]; d = ei[EE + e]; eid = e;
        dot = 0.f;
        const float* eap = ea + (size_t)e * FEA;
#pragma unroll
        for (int k = 0; k < FEA; k++) dot += __ldcs(&eap[k]) * We_s[k];
    } else {
        s = e - EE; d = s; eid = EE;
        dot = mdot;
    }
    int pos = atomicAdd(&g_cur[d], 1);
    g_csrc[pos] = s;
    g_ceid[pos] = eid;
    g_E3[pos] = dot;
}

// ---------------- tensor-core egemm v2: tf32 mma + smem-staged coalesced stores -------
// Block: 128 edges x 384 cols (E1 256 | E2 128). Warp w owns col groups {w+8j}, j<6.
// Per 16-row group: mma -> stage fp16 tile in smem -> cooperative uint4 row stores.
__global__ void __launch_bounds__(256)
egemm_mma_kernel(const float* __restrict__ ea,
                 const float* __restrict__ We1, const float* __restrict__ We2,
                 __half* __restrict__ E1, __half* __restrict__ E2) {
    __shared__ unsigned sA[128 * 17];      // [row][k] tf32, padded
    __shared__ unsigned sBt[384 * 17];     // [col][k] tf32, padded
    __shared__ __half sStage[16 * 392];    // 16 rows x 384 cols, padded to 392
    int tid = threadIdx.x;
    int warp = tid >> 5, lane = tid & 31;
    int g = lane >> 2, tg = lane & 3;
    int e0 = blockIdx.x * 128;

    // load A (tf32): thread -> (row = tid>>1, k-half q = tid&1)
    {
        int row = tid >> 1, q = tid & 1;
        int e = e0 + row;
        float4 v0 = make_float4(0.f, 0.f, 0.f, 0.f), v1 = v0;
        if (e < EE) {
            const float4* p = reinterpret_cast<const float4*>(ea + (size_t)e * 16 + q * 8);
            v0 = __ldcs(&p[0]);
            v1 = __ldcs(&p[1]);
        }
        unsigned* dst = &sA[row * 17 + q * 8];
        dst[0] = to_tf32(v0.x); dst[1] = to_tf32(v0.y);
        dst[2] = to_tf32(v0.z); dst[3] = to_tf32(v0.w);
        dst[4] = to_tf32(v1.x); dst[5] = to_tf32(v1.y);
        dst[6] = to_tf32(v1.z); dst[7] = to_tf32(v1.w);
    }
    // load B transposed (tf32): sBt[c][k], c in [0,384)
    for (int idx = tid; idx < 384 * 16; idx += 256) {
        int c = idx >> 4, k = idx & 15;
        float v = (c < 256) ? We1[k * 256 + c] : We2[k * 128 + (c - 256)];
        sBt[c * 17 + k] = to_tf32(v);
    }
    __syncthreads();

    // preload B fragments: 6 col groups x 2 k-halves x {b0,b1}
    unsigned bf[6][2][2];
    int cbs[6];
#pragma unroll
    for (int j = 0; j < 6; j++) {
        int cb = (warp + j * 8) * 8;
        cbs[j] = cb;
        const unsigned* bp = &sBt[(cb + g) * 17];
        bf[j][0][0] = bp[tg];     bf[j][0][1] = bp[tg + 4];
        bf[j][1][0] = bp[8 + tg]; bf[j][1][1] = bp[8 + tg + 4];
    }

#pragma unroll
    for (int eg = 0; eg < 8; eg++) {
        int r0 = eg * 16;
        // A fragments for both k-halves
        const unsigned* apg  = &sA[(r0 + g) * 17];
        const unsigned* apg8 = &sA[(r0 + g + 8) * 17];
        unsigned a00 = apg[tg],      a01 = apg8[tg],      a02 = apg[tg + 4],      a03 = apg8[tg + 4];
        unsigned a10 = apg[8 + tg],  a11 = apg8[8 + tg],  a12 = apg[8 + tg + 4],  a13 = apg8[8 + tg + 4];
#pragma unroll
        for (int j = 0; j < 6; j++) {
            float c0 = 0.f, c1 = 0.f, c2 = 0.f, c3 = 0.f;
            asm volatile(
                "mma.sync.aligned.m16n8k8.row.col.f32.tf32.tf32.f32 "
                "{%0,%1,%2,%3}, {%4,%5,%6,%7}, {%8,%9}, {%0,%1,%2,%3};"
                : "+f"(c0), "+f"(c1), "+f"(c2), "+f"(c3)
                : "r"(a00), "r"(a01), "r"(a02), "r"(a03),
                  "r"(bf[j][0][0]), "r"(bf[j][0][1]));
            asm volatile(
                "mma.sync.aligned.m16n8k8.row.col.f32.tf32.tf32.f32 "
                "{%0,%1,%2,%3}, {%4,%5,%6,%7}, {%8,%9}, {%0,%1,%2,%3};"
                : "+f"(c0), "+f"(c1), "+f"(c2), "+f"(c3)
                : "r"(a10), "r"(a11), "r"(a12), "r"(a13),
                  "r"(bf[j][1][0]), "r"(bf[j][1][1]));
            __half2 h01 = __floats2half2_rn(c0, c1);
            __half2 h23 = __floats2half2_rn(c2, c3);
            int cc = cbs[j] + 2 * tg;
            *reinterpret_cast<__half2*>(&sStage[g * 392 + cc]) = h01;
            *reinterpret_cast<__half2*>(&sStage[(g + 8) * 392 + cc]) = h23;
        }
        __syncthreads();
        // cooperative coalesced stores: E1 rows (512B each), then E2 rows (256B each)
        {
            // E1: 16 rows x 32 uint4
            int it = tid;
#pragma unroll
            for (int rep = 0; rep < 2; rep++) {
                int row = it >> 5, c16 = it & 31;
                int ge = e0 + r0 + row;
                if (ge < EE) {
                    uint4 v = *reinterpret_cast<const uint4*>(&sStage[row * 392 + c16 * 8]);
                    __stcs(reinterpret_cast<uint4*>(E1 + (size_t)ge * 256 + c16 * 8), v);
                }
                it += 256;
            }
            // E2: 16 rows x 16 uint4
            int row = tid >> 4, c16 = tid & 15;
            int ge = e0 + r0 + row;
            if (ge < EE) {
                uint4 v = *reinterpret_cast<const uint4*>(&sStage[row * 392 + 256 + c16 * 8]);
                __stcs(reinterpret_cast<uint4*>(E2 + (size_t)ge * 128 + c16 * 8), v);
            }
        }
        __syncthreads();
    }
}

// ---------------- SGEMM 128x128 tile, 8x8/thread, f32x2 packed, double-buffered ----------------
template <int K, int M, bool FUSE_BN>
__global__ void __launch_bounds__(256, 2)
gemm_bias_v3(const float* __restrict__ A, const float* __restrict__ B,
             const float* __restrict__ bias, float* __restrict__ C, int n,
             const float* __restrict__ gam, const float* __restrict__ bet) {
    __shared__ float As[2][16][132];
    __shared__ float Bs[2][16][132];
    __shared__ float sSc[FUSE_BN ? K : 1];
    __shared__ float sSh[FUSE_BN ? K : 1];
    constexpr int KT = K / 16;
    int tid = threadIdx.x;
    int tx = tid & 15, ty = tid >> 4;
    int row0 = blockIdx.y * 128, col0 = blockIdx.x * 128;

    if (FUSE_BN) {
        for (int j = tid; j < K; j += 256) {
            double mu = g_sums1[j] / (double)NN;
            double var = g_sumsq1[j] / (double)NN - mu * mu;
            float sc = gam[j] * rsqrtf((float)var + 1e-5f);
            sSc[j] = sc;
            sSh[j] = bet[j] - sc * (float)mu;
        }
        __syncthreads();
    }

    int a_r = tid >> 2, a_q = tid & 3;
    int b_kr = tid >> 5, b_cq = tid & 31;

    float4 aR[2], bR[2];
    auto bnf = [&](float a, int k) -> float {
        if (!FUSE_BN) return a;
        float y = sSc[k] * a + sSh[k];
        return y > 0.f ? y : (__expf(y) - 1.f);
    };
    auto loadG = [&](int kk) {
#pragma unroll
        for (int u = 0; u < 2; u++) {
            int grow = row0 + a_r + u * 64;
            aR[u] = (grow < n) ? reinterpret_cast<const float4*>(A + (size_t)grow * K + kk)[a_q]
                               : make_float4(0.f, 0.f, 0.f, 0.f);
            bR[u] = reinterpret_cast<const float4*>(B + (size_t)(kk + b_kr + u * 8) * M + col0)[b_cq];
        }
    };
    auto storeS = [&](int buf, int kk) {
#pragma unroll
        for (int u = 0; u < 2; u++) {
            int r = a_r + u * 64;
            As[buf][a_q * 4 + 0][r] = bnf(aR[u].x, kk + a_q * 4 + 0);
            As[buf][a_q * 4 + 1][r] = bnf(aR[u].y, kk + a_q * 4 + 1);
            As[buf][a_q * 4 + 2][r] = bnf(aR[u].z, kk + a_q * 4 + 2);
            As[buf][a_q * 4 + 3][r] = bnf(aR[u].w, kk + a_q * 4 + 3);
            reinterpret_cast<float4*>(&Bs[buf][b_kr + u * 8][0])[b_cq] = bR[u];
        }
    };

    unsigned long long acc[8][4];
#pragma unroll
    for (int i = 0; i < 8; i++)
#pragma unroll
        for (int j = 0; j < 4; j++) acc[i][j] = pack2(0.f, 0.f);

    loadG(0);
    storeS(0, 0);
    __syncthreads();
#pragma unroll
    for (int kt = 0; kt < KT; kt++) {
        if (kt + 1 < KT) loadG((kt + 1) * 16);
        int cur = kt & 1;
#pragma unroll
        for (int k = 0; k < 16; k++) {
            float a[8];
            float4 b4[2];
            *reinterpret_cast<float4*>(a)     = *reinterpret_cast<const float4*>(&As[cur][k][ty * 8]);
            *reinterpret_cast<float4*>(a + 4) = *reinterpret_cast<const float4*>(&As[cur][k][ty * 8 + 4]);
            b4[0] = *reinterpret_cast<const float4*>(&Bs[cur][k][tx * 8]);
            b4[1] = *reinterpret_cast<const float4*>(&Bs[cur][k][tx * 8 + 4]);
            const unsigned long long* bv = reinterpret_cast<const unsigned long long*>(b4);
#pragma unroll
            for (int i = 0; i < 8; i++) {
                unsigned long long av = pack2(a[i], a[i]);
#pragma unroll
                for (int j = 0; j < 4; j++) fma2(acc[i][j], av, bv[j]);
            }
        }
        if (kt + 1 < KT) {
            storeS((kt + 1) & 1, (kt + 1) * 16);
            __syncthreads();
        }
    }
    float4 bv0 = reinterpret_cast<const float4*>(bias + col0 + tx * 8)[0];
    float4 bv1 = reinterpret_cast<const float4*>(bias + col0 + tx * 8)[1];
    float bb[8] = {bv0.x, bv0.y, bv0.z, bv0.w, bv1.x, bv1.y, bv1.z, bv1.w};
#pragma unroll
    for (int i = 0; i < 8; i++) {
        int r = row0 + ty * 8 + i;
        if (r < n) {
            float w[8];
#pragma unroll
            for (int j = 0; j < 4; j++) {
                float2 p = unpack2(acc[i][j]);
                w[j * 2] = p.x + bb[j * 2];
                w[j * 2 + 1] = p.y + bb[j * 2 + 1];
            }
            float4* cp = reinterpret_cast<float4*>(C + (size_t)r * M + col0 + tx * 8);
            cp[0] = make_float4(w[0], w[1], w[2], w[3]);
            cp[1] = make_float4(w[4], w[5], w[6], w[7]);
        }
    }
}

// ---------------- warp-persistent GATv2 attention + register BN accumulation ----------
template <int D>
__global__ void __launch_bounds__(256)
gat_node_kernel(const float* __restrict__ xl, const __half* __restrict__ E,
                const float* __restrict__ att, float* __restrict__ outx,
                double* __restrict__ sums, double* __restrict__ sumsq) {
    constexpr int CPL = D / 32;
    constexpr int NC4 = CPL / 4;
    __shared__ float bsum[8][D];
    __shared__ float bsq[8][D];
    int w = threadIdx.x >> 5;
    int lane = threadIdx.x & 31;

    const float4* at4 = reinterpret_cast<const float4*>(att);
    float4 attv[NC4];
    float fsum[CPL], fsq[CPL];
#pragma unroll
    for (int v = 0; v < NC4; v++) attv[v] = at4[lane * NC4 + v];
#pragma unroll
    for (int c = 0; c < CPL; c++) { fsum[c] = 0.f; fsq[c] = 0.f; }

    auto load_er = [&](int eid, uint4& er) {
        if (NC4 == 2) {
            er = __ldcs(reinterpret_cast<const uint4*>(E + (size_t)eid * D) + lane);
        } else {
            uint2 t = __ldcs(reinterpret_cast<const uint2*>(E + (size_t)eid * D) + lane);
            er.x = t.x; er.y = t.y; er.z = 0u; er.w = 0u;
        }
    };

    for (int g = blockIdx.x * 8 + w; g < NN; g += GAT_BLOCKS * 8) {
        int node = g_nodeperm[g];
        int beg = g_rows[node], end = g_rows[node + 1];
        const float4* xd4 = reinterpret_cast<const float4*>(xl + (size_t)node * D);
        float4 xdv[NC4], accv[NC4];
        float den = 0.f;
#pragma unroll
        for (int v = 0; v < NC4; v++) {
            xdv[v] = xd4[lane * NC4 + v];
            accv[v] = make_float4(0.f, 0.f, 0.f, 0.f);
        }

        auto edge_compute = [&](const float4 (&xs)[NC4], const uint4& er) {
            float p = 0.f;
#pragma unroll
            for (int v = 0; v < NC4; v++) {
                unsigned w0 = (v == 0) ? er.x : er.z;
                unsigned w1 = (v == 0) ? er.y : er.w;
                float2 e01 = __half22float2(*reinterpret_cast<const __half2*>(&w0));
                float2 e23 = __half22float2(*reinterpret_cast<const __half2*>(&w1));
                float m0 = xs[v].x + xdv[v].x + e01.x;
                float m1 = xs[v].y + xdv[v].y + e01.y;
                float m2 = xs[v].z + xdv[v].z + e23.x;
                float m3 = xs[v].w + xdv[v].w + e23.y;
                float l0 = m0 > 0.f ? m0 : 0.2f * m0;
                float l1 = m1 > 0.f ? m1 : 0.2f * m1;
                float l2 = m2 > 0.f ? m2 : 0.2f * m2;
                float l3 = m3 > 0.f ? m3 : 0.2f * m3;
                p += l0 * attv[v].x + l1 * attv[v].y + l2 * attv[v].z + l3 * attv[v].w;
            }
            p += __shfl_xor_sync(0xffffffffu, p, 1);
            p += __shfl_xor_sync(0xffffffffu, p, 2);
            float ev = __expf(p);
            den += ev;
#pragma unroll
            for (int v = 0; v < NC4; v++) {
                accv[v].x += ev * xs[v].x;
                accv[v].y += ev * xs[v].y;
                accv[v].z += ev * xs[v].z;
                accv[v].w += ev * xs[v].w;
            }
        };

        int i = beg;
        for (; i + 4 <= end; i += 4) {
            int s0 = g_csrc[i], s1 = g_csrc[i + 1], s2 = g_csrc[i + 2], s3 = g_csrc[i + 3];
            int e0 = g_ceid[i], e1 = g_ceid[i + 1], e2 = g_ceid[i + 2], e3 = g_ceid[i + 3];
            float4 xs0[NC4], xs1[NC4], xs2[NC4], xs3[NC4];
            uint4 er0, er1, er2, er3;
            const float4* a0 = reinterpret_cast<const float4*>(xl + (size_t)s0 * D);
            const float4* a1 = reinterpret_cast<const float4*>(xl + (size_t)s1 * D);
            const float4* a2 = reinterpret_cast<const float4*>(xl + (size_t)s2 * D);
            const float4* a3 = reinterpret_cast<const float4*>(xl + (size_t)s3 * D);
#pragma unroll
            for (int v = 0; v < NC4; v++) {
                xs0[v] = a0[lane * NC4 + v];
                xs1[v] = a1[lane * NC4 + v];
                xs2[v] = a2[lane * NC4 + v];
                xs3[v] = a3[lane * NC4 + v];
            }
            load_er(e0, er0); load_er(e1, er1); load_er(e2, er2); load_er(e3, er3);
            edge_compute(xs0, er0);
            edge_compute(xs1, er1);
            edge_compute(xs2, er2);
            edge_compute(xs3, er3);
        }
        for (; i < end; i++) {
            int s0 = g_csrc[i];
            int e0 = g_ceid[i];
            float4 xs0[NC4];
            uint4 er0;
            const float4* a0 = reinterpret_cast<const float4*>(xl + (size_t)s0 * D);
#pragma unroll
            for (int v = 0; v < NC4; v++) xs0[v] = a0[lane * NC4 + v];
            load_er(e0, er0);
            edge_compute(xs0, er0);
        }

        float4* o4 = reinterpret_cast<float4*>(outx + (size_t)node * D);
        float inv = 1.f / (den + 1e-16f);
#pragma unroll
        for (int v = 0; v < NC4; v++) {
            float4 o = make_float4(accv[v].x * inv, accv[v].y * inv,
                                   accv[v].z * inv, accv[v].w * inv);
            o4[lane * NC4 + v] = o;
            fsum[v * 4 + 0] += o.x; fsq[v * 4 + 0] += o.x * o.x;
            fsum[v * 4 + 1] += o.y; fsq[v * 4 + 1] += o.y * o.y;
            fsum[v * 4 + 2] += o.z; fsq[v * 4 + 2] += o.z * o.z;
            fsum[v * 4 + 3] += o.w; fsq[v * 4 + 3] += o.w * o.w;
        }
    }

#pragma unroll
    for (int c = 0; c < CPL; c++) {
        bsum[w][lane * CPL + c] = fsum[c];
        bsq[w][lane * CPL + c] = fsq[c];
    }
    __syncthreads();
    int c = threadIdx.x;
    if (c < D) {
        float s = 0.f, s2 = 0.f;
#pragma unroll
        for (int u = 0; u < 8; u++) { s += bsum[u][c]; s2 += bsq[u][c]; }
        atomicAdd(&sums[c], (double)s);
        atomicAdd(&sumsq[c], (double)s2);
    }
}

// ---------------- layer 3: BN+ELU fused into the two scalar transforms ----------------
__global__ void lin3_kernel(const float* __restrict__ h2,
                            const float* __restrict__ gam, const float* __restrict__ bet,
                            const float* __restrict__ W3l, const float* __restrict__ b3l,
                            const float* __restrict__ W3r, const float* __restrict__ b3r) {
    __shared__ float sSc[128], sSh[128];
    int tid = threadIdx.x;
    if (tid < 128) {
        double mu = g_sums2[tid] / (double)NN;
        double var = g_sumsq2[tid] / (double)NN - mu * mu;
        float sc = gam[tid] * rsqrtf((float)var + 1e-5f);
        sSc[tid] = sc;
        sSh[tid] = bet[tid] - sc * (float)mu;
    }
    __syncthreads();
    int w = blockIdx.x * 8 + (tid >> 5);
    if (w >= NN) return;
    int lane = tid & 31;
    const float* row = h2 + (size_t)w * 128;
    float sl = 0.f, sr = 0.f;
#pragma unroll
    for (int q = 0; q < 4; q++) {
        int j = q * 32 + lane;
        float v = sSc[j] * row[j] + sSh[j];
        v = v > 0.f ? v : (__expf(v) - 1.f);
        sl += v * W3l[j];
        sr += v * W3r[j];
    }
#pragma unroll
    for (int off = 16; off >= 1; off >>= 1) {
        sl += __shfl_down_sync(0xffffffffu, sl, off);
        sr += __shfl_down_sync(0xffffffffu, sr, off);
    }
    if (lane == 0) {
        g_xl3[w] = sl + b3l[0];
        g_xr3[w] = sr + b3r[0];
    }
}

__global__ void gat3_kernel(float* __restrict__ out, const float* __restrict__ att3,
                            const float* __restrict__ bo3) {
    int node = blockIdx.x * 8 + (threadIdx.x >> 5);
    if (node >= NN) return;
    int lane = threadIdx.x & 31;
    int beg = g_rows[node], end = g_rows[node + 1];
    float xr = g_xr3[node];
    float a3 = att3[0];
    float num = 0.f, den = 0.f;
    for (int i = beg + lane; i < end; i += 32) {
        int s = g_csrc[i];
        float xls = g_xl3[s];
        float m = xls + xr + g_E3[i];
        float lg = (m > 0.f ? m : 0.2f * m) * a3;
        float ev = __expf(lg);
        den += ev;
        num += ev * xls;
    }
#pragma unroll
    for (int off = 16; off >= 1; off >>= 1) {
        num += __shfl_down_sync(0xffffffffu, num, off);
        den += __shfl_down_sync(0xffffffffu, den, off);
    }
    if (lane == 0) out[node] = num / (den + 1e-16f) + bo3[0];
}

// ---------------- host launch ----------------
extern "C" void kernel_launch(void* const* d_in, const int* in_sizes, int n_in,
                              void* d_out, int out_size) {
    const float* x    = (const float*)d_in[0];
    const int*   ei   = (const int*)d_in[1];
    const float* ea   = (const float*)d_in[2];
    const float* W1   = (const float*)d_in[3];
    const float* b1   = (const float*)d_in[4];
    const float* We1  = (const float*)d_in[5];
    const float* att1 = (const float*)d_in[6];
    // d_in[7] = bo1: cancels in BatchNorm
    const float* g1   = (const float*)d_in[8];
    const float* bt1  = (const float*)d_in[9];
    const float* W2   = (const float*)d_in[10];
    const float* b2   = (const float*)d_in[11];
    const float* We2  = (const float*)d_in[12];
    const float* att2 = (const float*)d_in[13];
    // d_in[14] = bo2: cancels in BatchNorm
    const float* g2   = (const float*)d_in[15];
    const float* bt2  = (const float*)d_in[16];
    const float* W3l  = (const float*)d_in[17];
    const float* b3l  = (const float*)d_in[18];
    const float* W3r  = (const float*)d_in[19];
    const float* b3r  = (const float*)d_in[20];
    const float* We3  = (const float*)d_in[21];
    const float* att3 = (const float*)d_in[22];
    const float* bo3  = (const float*)d_in[23];
    float* out = (float*)d_out;

    float *xl1, *acc1, *xl2, *acc2;
    __half *E1, *E2;
    double *sums1, *sumsq1, *sums2, *sumsq2;
    cudaGetSymbolAddress((void**)&xl1,  g_xl1);
    cudaGetSymbolAddress((void**)&acc1, g_acc1);
    cudaGetSymbolAddress((void**)&xl2,  g_xl2);
    cudaGetSymbolAddress((void**)&acc2, g_acc2);
    cudaGetSymbolAddress((void**)&E1,   g_E1);
    cudaGetSymbolAddress((void**)&E2,   g_E2);
    cudaGetSymbolAddress((void**)&sums1, g_sums1);
    cudaGetSymbolAddress((void**)&sumsq1, g_sumsq1);
    cudaGetSymbolAddress((void**)&sums2, g_sums2);
    cudaGetSymbolAddress((void**)&sumsq2, g_sumsq2);

    static cudaStream_t sB = nullptr, sC = nullptr;
    static cudaEvent_t evFork = nullptr, evG1 = nullptr, evEg = nullptr;
    if (sB == nullptr) {
        cudaStreamCreateWithFlags(&sB, cudaStreamNonBlocking);
        cudaStreamCreateWithFlags(&sC, cudaStreamNonBlocking);
        cudaEventCreateWithFlags(&evFork, cudaEventDisableTiming);
        cudaEventCreateWithFlags(&evG1, cudaEventDisableTiming);
        cudaEventCreateWithFlags(&evEg, cudaEventDisableTiming);
    }

    // fork: gemm1 (sB) and the tf32-mma egemm (sC) overlap prep (main)
    cudaEventRecord(evFork, 0);
    cudaStreamWaitEvent(sB, evFork, 0);
    cudaStreamWaitEvent(sC, evFork, 0);

    prep_hist_ea_kernel<<<HIST_BLKS + 512, 256>>>(ei, ea);                         // launch 1
    gemm_bias_v3<128, 256, false><<<dim3(2, (NN + 127) / 128), 256, 0, sB>>>(
        x, W1, b1, xl1, NN, nullptr, nullptr);                                     // launch 2
    cudaEventRecord(evG1, sB);
    scan1_kernel<<<NB, 256>>>();                                                   // launch 3
    egemm_mma_kernel<<<(EE + 127) / 128, 256, 0, sC>>>(ea, We1, We2, E1, E2);      // launch 4 <- profiled
    cudaEventRecord(evEg, sC);

    scan2_kernel<<<1, 256>>>();                                                    // launch 5
    scan3_kernel<<<NB, 256>>>();                                                   // launch 6
    csr_scatter_kernel<<<(ETOT + 255) / 256, 256>>>(ei, ea, We3, We1, We2, E1, E2);// launch 7

    // layer 1 attention: needs xl1 (sB) + E1 (sC) + CSR (main)
    cudaStreamWaitEvent(0, evG1, 0);
    cudaStreamWaitEvent(0, evEg, 0);
    gat_node_kernel<256><<<GAT_BLOCKS, 256>>>(xl1, E1, att1, acc1, sums1, sumsq1); // launch 8

    // layer 2
    gemm_bias_v3<256, 128, true><<<dim3(1, (NN + 127) / 128), 256>>>(
        acc1, W2, b2, xl2, NN, g1, bt1);                                           // launch 9
    gat_node_kernel<128><<<GAT_BLOCKS, 256>>>(xl2, E2, att2, acc2, sums2, sumsq2); // launch 10

    // layer 3
    lin3_kernel<<<(NN + 7) / 8, 256>>>(acc2, g2, bt2, W3l, b3l, W3r, b3r);         // launch 11
    gat3_kernel<<<(NN + 7) / 8, 256>>>(out, att3, bo3);                            // launch 12
}

// round 15
// speedup vs baseline: 1.1352x; 1.0947x over previous
#include <cuda_runtime.h>
#include <cuda_fp16.h>
#include <math.h>

#define NN 50000
#define EE 500000
#define ETOT 550000
#define FEA 16
#define NB 196   // ceil(NN/256)
#define GAT_BLOCKS 1184   // 148 SMs * 8 blocks -> one wave

// ---------------- packed f32x2 helpers (Blackwell dual-lane fp32) ----------------
__device__ __forceinline__ unsigned long long pack2(float x, float y) {
    unsigned long long r;
    asm("mov.b64 %0, {%1, %2};" : "=l"(r) : "f"(x), "f"(y));
    return r;
}
__device__ __forceinline__ void fma2(unsigned long long& d, unsigned long long a,
                                     unsigned long long b) {
    asm("fma.rn.f32x2 %0, %1, %2, %0;" : "+l"(d) : "l"(a), "l"(b));
}
__device__ __forceinline__ float2 unpack2(unsigned long long v) {
    float lo, hi;
    asm("mov.b64 {%0, %1}, %2;" : "=f"(lo), "=f"(hi) : "l"(v));
    return make_float2(lo, hi);
}
__device__ __forceinline__ unsigned to_tf32(float v) {
    unsigned r;
    asm("cvt.rna.tf32.f32 %0, %1;" : "=r"(r) : "f"(v));
    return r;
}

// ---------------- scratch (static device globals; no allocation) ----------------
__device__ float  g_xl1[NN * 256];
__device__ float  g_acc1[NN * 256];
__device__ float  g_xl2[NN * 128];
__device__ float  g_acc2[NN * 128];
__device__ __half g_E1[(EE + 1) * 256];   // edge transform, EID order (+1 self-loop row)
__device__ __half g_E2[(EE + 1) * 128];
__device__ float  g_E3[ETOT];             // CSR order
__device__ float  g_xl3[NN];
__device__ float  g_xr3[NN];
__device__ int    g_cnt[NN];
__device__ int    g_rows[NN + 1];
__device__ int    g_cur[NN];
__device__ int    g_csrc[ETOT];
__device__ int    g_ceid[ETOT];
__device__ int    g_bsums[256];
__device__ int    g_dhist[64];
__device__ int    g_dcur[64];
__device__ int    g_nodeperm[NN];
__device__ double g_sums1[256];
__device__ double g_sumsq1[256];
__device__ double g_sums2[128];
__device__ double g_sumsq2[128];
__device__ double g_easum[FEA];
__device__ float  g_eamean[FEA];

// ---------------- prep: dst histogram + edge_attr column sums (merged) ----------------
#define HIST_BLKS 1954
__global__ void prep_hist_ea_kernel(const int* __restrict__ ei, const float* __restrict__ ea) {
    if (blockIdx.x < HIST_BLKS) {
        int e = blockIdx.x * 256 + threadIdx.x;
        if (e < EE) atomicAdd(&g_cnt[__ldcs(&ei[EE + e])], 1);
    } else {
        long tid = (long)(blockIdx.x - HIST_BLKS) * 256 + threadIdx.x;
        long stride = 512L * 256;
        int k = (int)(tid & 15);
        double sv = 0.0;
        for (long i = tid; i < (long)EE * FEA; i += stride) sv += (double)__ldcs(&ea[i]);
        atomicAdd(&g_easum[k], sv);
    }
}

// ---------------- CSR scan chain (+ degree histogram for node sort) ----------------
__global__ void scan1_kernel() {
    __shared__ int s[256];
    int t = threadIdx.x;
    int i = blockIdx.x * 256 + t;
    int v = 0;
    if (i < NN) {
        v = g_cnt[i] + 1;   // +1 self loop
        g_cnt[i] = v;
        atomicAdd(&g_dhist[min(v, 63)], 1);
    }
    s[t] = v;
    __syncthreads();
#pragma unroll
    for (int off = 1; off < 256; off <<= 1) {
        int x = (t >= off) ? s[t - off] : 0;
        __syncthreads();
        s[t] += x;
        __syncthreads();
    }
    if (i < NN) g_rows[i] = s[t];
    if (t == 255) g_bsums[blockIdx.x] = s[255];
}
__global__ void scan2_kernel() {
    __shared__ int s[256];
    int t = threadIdx.x;
    if (t < FEA) {
        g_eamean[t] = (float)(g_easum[t] / (double)EE);
        g_easum[t] = 0.0;
    }
    g_sums1[t] = 0.0; g_sumsq1[t] = 0.0;
    if (t < 128) { g_sums2[t] = 0.0; g_sumsq2[t] = 0.0; }
    int v = (t < NB) ? g_bsums[t] : 0;
    s[t] = v;
    __syncthreads();
#pragma unroll
    for (int off = 1; off < 256; off <<= 1) {
        int x = (t >= off) ? s[t - off] : 0;
        __syncthreads();
        s[t] += x;
        __syncthreads();
    }
    g_bsums[t] = s[t] - v;
    __syncthreads();
    int dv = (t < 64) ? g_dhist[t] : 0;
    s[t] = dv;
    __syncthreads();
#pragma unroll
    for (int off = 1; off < 64; off <<= 1) {
        int x = (t >= off) ? s[t - off] : 0;
        __syncthreads();
        s[t] += x;
        __syncthreads();
    }
    if (t < 64) g_dcur[t] = NN - s[t];
}
__global__ void scan3_kernel() {
    int i = blockIdx.x * blockDim.x + threadIdx.x;
    if (i < NN) {
        int deg = g_cnt[i];
        int r = g_rows[i] - deg + g_bsums[i >> 8];
        g_rows[i] = r;
        g_cur[i] = r;
        int pos = atomicAdd(&g_dcur[min(deg, 63)], 1);
        g_nodeperm[pos] = i;
    }
    if (i == 0) g_rows[NN] = ETOT;
}
// CSR scatter + E3 + self-loop rows of E1/E2; resets g_cnt/g_dhist
__global__ void csr_scatter_kernel(const int* __restrict__ ei, const float* __restrict__ ea,
                                   const float* __restrict__ We3,
                                   const float* __restrict__ We1, const float* __restrict__ We2,
                                   __half* __restrict__ E1, __half* __restrict__ E2) {
    __shared__ float We_s[FEA];
    __shared__ float mean_s[FEA];
    __shared__ float mdot;
    if (threadIdx.x < FEA) {
        We_s[threadIdx.x] = We3[threadIdx.x];
        mean_s[threadIdx.x] = g_eamean[threadIdx.x];
    }
    __syncthreads();
    if (threadIdx.x == 0) {
        float s = 0.f;
#pragma unroll
        for (int k = 0; k < FEA; k++) s += mean_s[k] * We_s[k];
        mdot = s;
    }
    __syncthreads();
    if (blockIdx.x == 0) {
        int c = threadIdx.x;
        {
            float s = 0.f;
#pragma unroll
            for (int k = 0; k < FEA; k++) s += mean_s[k] * We1[k * 256 + c];
            E1[(size_t)EE * 256 + c] = __float2half_rn(s);
        }
        if (c < 128) {
            float s = 0.f;
#pragma unroll
            for (int k = 0; k < FEA; k++) s += mean_s[k] * We2[k * 128 + c];
            E2[(size_t)EE * 128 + c] = __float2half_rn(s);
        }
    }
    int e = blockIdx.x * blockDim.x + threadIdx.x;
    if (e >= ETOT) return;
    if (e < NN) g_cnt[e] = 0;
    if (e < 64) g_dhist[e] = 0;
    int s, d, eid;
    float dot;
    if (e < EE) {
        s = ei[e]; d = ei[EE + e]; eid = e;
        dot = 0.f;
        const float* eap = ea + (size_t)e * FEA;
#pragma unroll
        for (int k = 0; k < FEA; k++) dot += __ldcs(&eap[k]) * We_s[k];
    } else {
        s = e - EE; d = s; eid = EE;
        dot = mdot;
    }
    int pos = atomicAdd(&g_cur[d], 1);
    g_csrc[pos] = s;
    g_ceid[pos] = eid;
    g_E3[pos] = dot;
}

// ---------------- tensor-core egemm v3: tf32 mma, B fragments from global, staged stores
// Block: 128 edges x 384 cols. Warp w owns col groups {w+8j}, j<6. smem ~21KB -> high occ.
__global__ void __launch_bounds__(256)
egemm_mma_kernel(const float* __restrict__ ea,
                 const float* __restrict__ We1, const float* __restrict__ We2,
                 __half* __restrict__ E1, __half* __restrict__ E2) {
    __shared__ unsigned sA[128 * 17];      // [row][k] tf32, padded
    __shared__ __half sStage[16 * 392];    // 16 rows x 384 cols, padded to 392
    int tid = threadIdx.x;
    int warp = tid >> 5, lane = tid & 31;
    int g = lane >> 2, tg = lane & 3;
    int e0 = blockIdx.x * 128;

    // load A (tf32): thread -> (row = tid>>1, k-half q = tid&1)
    {
        int row = tid >> 1, q = tid & 1;
        int e = e0 + row;
        float4 v0 = make_float4(0.f, 0.f, 0.f, 0.f), v1 = v0;
        if (e < EE) {
            const float4* p = reinterpret_cast<const float4*>(ea + (size_t)e * 16 + q * 8);
            v0 = __ldcs(&p[0]);
            v1 = __ldcs(&p[1]);
        }
        unsigned* dst = &sA[row * 17 + q * 8];
        dst[0] = to_tf32(v0.x); dst[1] = to_tf32(v0.y);
        dst[2] = to_tf32(v0.z); dst[3] = to_tf32(v0.w);
        dst[4] = to_tf32(v1.x); dst[5] = to_tf32(v1.y);
        dst[6] = to_tf32(v1.z); dst[7] = to_tf32(v1.w);
    }

    // B fragments straight from global (We is tiny & L1/L2-resident).
    // Fragment col = cb + g; k rows {tg, tg+4} (half0) and {8+tg, 12+tg} (half1).
    unsigned bf[6][2][2];
    int cbs[6];
#pragma unroll
    for (int j = 0; j < 6; j++) {
        int cb = (warp + j * 8) * 8;
        cbs[j] = cb;
        int col = cb + g;
        const float* Bp;
        int ldb;
        if (cb < 256) { Bp = We1; ldb = 256; }
        else          { Bp = We2; ldb = 128; col -= 256; }
        bf[j][0][0] = to_tf32(__ldg(&Bp[(size_t)tg * ldb + col]));
        bf[j][0][1] = to_tf32(__ldg(&Bp[(size_t)(tg + 4) * ldb + col]));
        bf[j][1][0] = to_tf32(__ldg(&Bp[(size_t)(8 + tg) * ldb + col]));
        bf[j][1][1] = to_tf32(__ldg(&Bp[(size_t)(12 + tg) * ldb + col]));
    }
    __syncthreads();

#pragma unroll
    for (int eg = 0; eg < 8; eg++) {
        int r0 = eg * 16;
        const unsigned* apg  = &sA[(r0 + g) * 17];
        const unsigned* apg8 = &sA[(r0 + g + 8) * 17];
        unsigned a00 = apg[tg],      a01 = apg8[tg],      a02 = apg[tg + 4],      a03 = apg8[tg + 4];
        unsigned a10 = apg[8 + tg],  a11 = apg8[8 + tg],  a12 = apg[8 + tg + 4],  a13 = apg8[8 + tg + 4];
#pragma unroll
        for (int j = 0; j < 6; j++) {
            float c0 = 0.f, c1 = 0.f, c2 = 0.f, c3 = 0.f;
            asm volatile(
                "mma.sync.aligned.m16n8k8.row.col.f32.tf32.tf32.f32 "
                "{%0,%1,%2,%3}, {%4,%5,%6,%7}, {%8,%9}, {%0,%1,%2,%3};"
                : "+f"(c0), "+f"(c1), "+f"(c2), "+f"(c3)
                : "r"(a00), "r"(a01), "r"(a02), "r"(a03),
                  "r"(bf[j][0][0]), "r"(bf[j][0][1]));
            asm volatile(
                "mma.sync.aligned.m16n8k8.row.col.f32.tf32.tf32.f32 "
                "{%0,%1,%2,%3}, {%4,%5,%6,%7}, {%8,%9}, {%0,%1,%2,%3};"
                : "+f"(c0), "+f"(c1), "+f"(c2), "+f"(c3)
                : "r"(a10), "r"(a11), "r"(a12), "r"(a13),
                  "r"(bf[j][1][0]), "r"(bf[j][1][1]));
            __half2 h01 = __floats2half2_rn(c0, c1);
            __half2 h23 = __floats2half2_rn(c2, c3);
            int cc = cbs[j] + 2 * tg;
            *reinterpret_cast<__half2*>(&sStage[g * 392 + cc]) = h01;
            *reinterpret_cast<__half2*>(&sStage[(g + 8) * 392 + cc]) = h23;
        }
        __syncthreads();
        // cooperative coalesced stores
        {
            int it = tid;
#pragma unroll
            for (int rep = 0; rep < 2; rep++) {
                int row = it >> 5, c16 = it & 31;
                int ge = e0 + r0 + row;
                if (ge < EE) {
                    uint4 v = *reinterpret_cast<const uint4*>(&sStage[row * 392 + c16 * 8]);
                    __stcs(reinterpret_cast<uint4*>(E1 + (size_t)ge * 256 + c16 * 8), v);
                }
                it += 256;
            }
            int row = tid >> 4, c16 = tid & 15;
            int ge = e0 + r0 + row;
            if (ge < EE) {
                uint4 v = *reinterpret_cast<const uint4*>(&sStage[row * 392 + 256 + c16 * 8]);
                __stcs(reinterpret_cast<uint4*>(E2 + (size_t)ge * 128 + c16 * 8), v);
            }
        }
        __syncthreads();
    }
}

// ---------------- SGEMM 128x128 tile, 8x8/thread, f32x2 packed, double-buffered ----------------
template <int K, int M, bool FUSE_BN>
__global__ void __launch_bounds__(256, 2)
gemm_bias_v3(const float* __restrict__ A, const float* __restrict__ B,
             const float* __restrict__ bias, float* __restrict__ C, int n,
             const float* __restrict__ gam, const float* __restrict__ bet) {
    __shared__ float As[2][16][132];
    __shared__ float Bs[2][16][132];
    __shared__ float sSc[FUSE_BN ? K : 1];
    __shared__ float sSh[FUSE_BN ? K : 1];
    constexpr int KT = K / 16;
    int tid = threadIdx.x;
    int tx = tid & 15, ty = tid >> 4;
    int row0 = blockIdx.y * 128, col0 = blockIdx.x * 128;

    if (FUSE_BN) {
        for (int j = tid; j < K; j += 256) {
            double mu = g_sums1[j] / (double)NN;
            double var = g_sumsq1[j] / (double)NN - mu * mu;
            float sc = gam[j] * rsqrtf((float)var + 1e-5f);
            sSc[j] = sc;
            sSh[j] = bet[j] - sc * (float)mu;
        }
        __syncthreads();
    }

    int a_r = tid >> 2, a_q = tid & 3;
    int b_kr = tid >> 5, b_cq = tid & 31;

    float4 aR[2], bR[2];
    auto bnf = [&](float a, int k) -> float {
        if (!FUSE_BN) return a;
        float y = sSc[k] * a + sSh[k];
        return y > 0.f ? y : (__expf(y) - 1.f);
    };
    auto loadG = [&](int kk) {
#pragma unroll
        for (int u = 0; u < 2; u++) {
            int grow = row0 + a_r + u * 64;
            aR[u] = (grow < n) ? reinterpret_cast<const float4*>(A + (size_t)grow * K + kk)[a_q]
                               : make_float4(0.f, 0.f, 0.f, 0.f);
            bR[u] = reinterpret_cast<const float4*>(B + (size_t)(kk + b_kr + u * 8) * M + col0)[b_cq];
        }
    };
    auto storeS = [&](int buf, int kk) {
#pragma unroll
        for (int u = 0; u < 2; u++) {
            int r = a_r + u * 64;
            As[buf][a_q * 4 + 0][r] = bnf(aR[u].x, kk + a_q * 4 + 0);
            As[buf][a_q * 4 + 1][r] = bnf(aR[u].y, kk + a_q * 4 + 1);
            As[buf][a_q * 4 + 2][r] = bnf(aR[u].z, kk + a_q * 4 + 2);
            As[buf][a_q * 4 + 3][r] = bnf(aR[u].w, kk + a_q * 4 + 3);
            reinterpret_cast<float4*>(&Bs[buf][b_kr + u * 8][0])[b_cq] = bR[u];
        }
    };

    unsigned long long acc[8][4];
#pragma unroll
    for (int i = 0; i < 8; i++)
#pragma unroll
        for (int j = 0; j < 4; j++) acc[i][j] = pack2(0.f, 0.f);

    loadG(0);
    storeS(0, 0);
    __syncthreads();
#pragma unroll
    for (int kt = 0; kt < KT; kt++) {
        if (kt + 1 < KT) loadG((kt + 1) * 16);
        int cur = kt & 1;
#pragma unroll
        for (int k = 0; k < 16; k++) {
            float a[8];
            float4 b4[2];
            *reinterpret_cast<float4*>(a)     = *reinterpret_cast<const float4*>(&As[cur][k][ty * 8]);
            *reinterpret_cast<float4*>(a + 4) = *reinterpret_cast<const float4*>(&As[cur][k][ty * 8 + 4]);
            b4[0] = *reinterpret_cast<const float4*>(&Bs[cur][k][tx * 8]);
            b4[1] = *reinterpret_cast<const float4*>(&Bs[cur][k][tx * 8 + 4]);
            const unsigned long long* bv = reinterpret_cast<const unsigned long long*>(b4);
#pragma unroll
            for (int i = 0; i < 8; i++) {
                unsigned long long av = pack2(a[i], a[i]);
#pragma unroll
                for (int j = 0; j < 4; j++) fma2(acc[i][j], av, bv[j]);
            }
        }
        if (kt + 1 < KT) {
            storeS((kt + 1) & 1, (kt + 1) * 16);
            __syncthreads();
        }
    }
    float4 bv0 = reinterpret_cast<const float4*>(bias + col0 + tx * 8)[0];
    float4 bv1 = reinterpret_cast<const float4*>(bias + col0 + tx * 8)[1];
    float bb[8] = {bv0.x, bv0.y, bv0.z, bv0.w, bv1.x, bv1.y, bv1.z, bv1.w};
#pragma unroll
    for (int i = 0; i < 8; i++) {
        int r = row0 + ty * 8 + i;
        if (r < n) {
            float w[8];
#pragma unroll
            for (int j = 0; j < 4; j++) {
                float2 p = unpack2(acc[i][j]);
                w[j * 2] = p.x + bb[j * 2];
                w[j * 2 + 1] = p.y + bb[j * 2 + 1];
            }
            float4* cp = reinterpret_cast<float4*>(C + (size_t)r * M + col0 + tx * 8);
            cp[0] = make_float4(w[0], w[1], w[2], w[3]);
            cp[1] = make_float4(w[4], w[5], w[6], w[7]);
        }
    }
}

// ---------------- warp-persistent GATv2 attention + register BN accumulation ----------
template <int D>
__global__ void __launch_bounds__(256)
gat_node_kernel(const float* __restrict__ xl, const __half* __restrict__ E,
                const float* __restrict__ att, float* __restrict__ outx,
                double* __restrict__ sums, double* __restrict__ sumsq) {
    constexpr int CPL = D / 32;
    constexpr int NC4 = CPL / 4;
    __shared__ float bsum[8][D];
    __shared__ float bsq[8][D];
    int w = threadIdx.x >> 5;
    int lane = threadIdx.x & 31;

    const float4* at4 = reinterpret_cast<const float4*>(att);
    float4 attv[NC4];
    float fsum[CPL], fsq[CPL];
#pragma unroll
    for (int v = 0; v < NC4; v++) attv[v] = at4[lane * NC4 + v];
#pragma unroll
    for (int c = 0; c < CPL; c++) { fsum[c] = 0.f; fsq[c] = 0.f; }

    auto load_er = [&](int eid, uint4& er) {
        if (NC4 == 2) {
            er = __ldcs(reinterpret_cast<const uint4*>(E + (size_t)eid * D) + lane);
        } else {
            uint2 t = __ldcs(reinterpret_cast<const uint2*>(E + (size_t)eid * D) + lane);
            er.x = t.x; er.y = t.y; er.z = 0u; er.w = 0u;
        }
    };

    for (int g = blockIdx.x * 8 + w; g < NN; g += GAT_BLOCKS * 8) {
        int node = g_nodeperm[g];
        int beg = g_rows[node], end = g_rows[node + 1];
        const float4* xd4 = reinterpret_cast<const float4*>(xl + (size_t)node * D);
        float4 xdv[NC4], accv[NC4];
        float den = 0.f;
#pragma unroll
        for (int v = 0; v < NC4; v++) {
            xdv[v] = xd4[lane * NC4 + v];
            accv[v] = make_float4(0.f, 0.f, 0.f, 0.f);
        }

        auto edge_compute = [&](const float4 (&xs)[NC4], const uint4& er) {
            float p = 0.f;
#pragma unroll
            for (int v = 0; v < NC4; v++) {
                unsigned w0 = (v == 0) ? er.x : er.z;
                unsigned w1 = (v == 0) ? er.y : er.w;
                float2 e01 = __half22float2(*reinterpret_cast<const __half2*>(&w0));
                float2 e23 = __half22float2(*reinterpret_cast<const __half2*>(&w1));
                float m0 = xs[v].x + xdv[v].x + e01.x;
                float m1 = xs[v].y + xdv[v].y + e01.y;
                float m2 = xs[v].z + xdv[v].z + e23.x;
                float m3 = xs[v].w + xdv[v].w + e23.y;
                float l0 = m0 > 0.f ? m0 : 0.2f * m0;
                float l1 = m1 > 0.f ? m1 : 0.2f * m1;
                float l2 = m2 > 0.f ? m2 : 0.2f * m2;
                float l3 = m3 > 0.f ? m3 : 0.2f * m3;
                p += l0 * attv[v].x + l1 * attv[v].y + l2 * attv[v].z + l3 * attv[v].w;
            }
            p += __shfl_xor_sync(0xffffffffu, p, 1);
            p += __shfl_xor_sync(0xffffffffu, p, 2);
            float ev = __expf(p);
            den += ev;
#pragma unroll
            for (int v = 0; v < NC4; v++) {
                accv[v].x += ev * xs[v].x;
                accv[v].y += ev * xs[v].y;
                accv[v].z += ev * xs[v].z;
                accv[v].w += ev * xs[v].w;
            }
        };

        int i = beg;
        for (; i + 4 <= end; i += 4) {
            int s0 = g_csrc[i], s1 = g_csrc[i + 1], s2 = g_csrc[i + 2], s3 = g_csrc[i + 3];
            int e0 = g_ceid[i], e1 = g_ceid[i + 1], e2 = g_ceid[i + 2], e3 = g_ceid[i + 3];
            float4 xs0[NC4], xs1[NC4], xs2[NC4], xs3[NC4];
            uint4 er0, er1, er2, er3;
            const float4* a0 = reinterpret_cast<const float4*>(xl + (size_t)s0 * D);
            const float4* a1 = reinterpret_cast<const float4*>(xl + (size_t)s1 * D);
            const float4* a2 = reinterpret_cast<const float4*>(xl + (size_t)s2 * D);
            const float4* a3 = reinterpret_cast<const float4*>(xl + (size_t)s3 * D);
#pragma unroll
            for (int v = 0; v < NC4; v++) {
                xs0[v] = a0[lane * NC4 + v];
                xs1[v] = a1[lane * NC4 + v];
                xs2[v] = a2[lane * NC4 + v];
                xs3[v] = a3[lane * NC4 + v];
            }
            load_er(e0, er0); load_er(e1, er1); load_er(e2, er2); load_er(e3, er3);
            edge_compute(xs0, er0);
            edge_compute(xs1, er1);
            edge_compute(xs2, er2);
            edge_compute(xs3, er3);
        }
        for (; i < end; i++) {
            int s0 = g_csrc[i];
            int e0 = g_ceid[i];
            float4 xs0[NC4];
            uint4 er0;
            const float4* a0 = reinterpret_cast<const float4*>(xl + (size_t)s0 * D);
#pragma unroll
            for (int v = 0; v < NC4; v++) xs0[v] = a0[lane * NC4 + v];
            load_er(e0, er0);
            edge_compute(xs0, er0);
        }

        float4* o4 = reinterpret_cast<float4*>(outx + (size_t)node * D);
        float inv = 1.f / (den + 1e-16f);
#pragma unroll
        for (int v = 0; v < NC4; v++) {
            float4 o = make_float4(accv[v].x * inv, accv[v].y * inv,
                                   accv[v].z * inv, accv[v].w * inv);
            o4[lane * NC4 + v] = o;
            fsum[v * 4 + 0] += o.x; fsq[v * 4 + 0] += o.x * o.x;
            fsum[v * 4 + 1] += o.y; fsq[v * 4 + 1] += o.y * o.y;
            fsum[v * 4 + 2] += o.z; fsq[v * 4 + 2] += o.z * o.z;
            fsum[v * 4 + 3] += o.w; fsq[v * 4 + 3] += o.w * o.w;
        }
    }

#pragma unroll
    for (int c = 0; c < CPL; c++) {
        bsum[w][lane * CPL + c] = fsum[c];
        bsq[w][lane * CPL + c] = fsq[c];
    }
    __syncthreads();
    int c = threadIdx.x;
    if (c < D) {
        float s = 0.f, s2 = 0.f;
#pragma unroll
        for (int u = 0; u < 8; u++) { s += bsum[u][c]; s2 += bsq[u][c]; }
        atomicAdd(&sums[c], (double)s);
        atomicAdd(&sumsq[c], (double)s2);
    }
}

// ---------------- layer 3: BN+ELU fused into the two scalar transforms ----------------
__global__ void lin3_kernel(const float* __restrict__ h2,
                            const float* __restrict__ gam, const float* __restrict__ bet,
                            const float* __restrict__ W3l, const float* __restrict__ b3l,
                            const float* __restrict__ W3r, const float* __restrict__ b3r) {
    __shared__ float sSc[128], sSh[128];
    int tid = threadIdx.x;
    if (tid < 128) {
        double mu = g_sums2[tid] / (double)NN;
        double var = g_sumsq2[tid] / (double)NN - mu * mu;
        float sc = gam[tid] * rsqrtf((float)var + 1e-5f);
        sSc[tid] = sc;
        sSh[tid] = bet[tid] - sc * (float)mu;
    }
    __syncthreads();
    int w = blockIdx.x * 8 + (tid >> 5);
    if (w >= NN) return;
    int lane = tid & 31;
    const float* row = h2 + (size_t)w * 128;
    float sl = 0.f, sr = 0.f;
#pragma unroll
    for (int q = 0; q < 4; q++) {
        int j = q * 32 + lane;
        float v = sSc[j] * row[j] + sSh[j];
        v = v > 0.f ? v : (__expf(v) - 1.f);
        sl += v * W3l[j];
        sr += v * W3r[j];
    }
#pragma unroll
    for (int off = 16; off >= 1; off >>= 1) {
        sl += __shfl_down_sync(0xffffffffu, sl, off);
        sr += __shfl_down_sync(0xffffffffu, sr, off);
    }
    if (lane == 0) {
        g_xl3[w] = sl + b3l[0];
        g_xr3[w] = sr + b3r[0];
    }
}

__global__ void gat3_kernel(float* __restrict__ out, const float* __restrict__ att3,
                            const float* __restrict__ bo3) {
    int node = blockIdx.x * 8 + (threadIdx.x >> 5);
    if (node >= NN) return;
    int lane = threadIdx.x & 31;
    int beg = g_rows[node], end = g_rows[node + 1];
    float xr = g_xr3[node];
    float a3 = att3[0];
    float num = 0.f, den = 0.f;
    for (int i = beg + lane; i < end; i += 32) {
        int s = g_csrc[i];
        float xls = g_xl3[s];
        float m = xls + xr + g_E3[i];
        float lg = (m > 0.f ? m : 0.2f * m) * a3;
        float ev = __expf(lg);
        den += ev;
        num += ev * xls;
    }
#pragma unroll
    for (int off = 16; off >= 1; off >>= 1) {
        num += __shfl_down_sync(0xffffffffu, num, off);
        den += __shfl_down_sync(0xffffffffu, den, off);
    }
    if (lane == 0) out[node] = num / (den + 1e-16f) + bo3[0];
}

// ---------------- host launch ----------------
extern "C" void kernel_launch(void* const* d_in, const int* in_sizes, int n_in,
                              void* d_out, int out_size) {
    const float* x    = (const float*)d_in[0];
    const int*   ei   = (const int*)d_in[1];
    const float* ea   = (const float*)d_in[2];
    const float* W1   = (const float*)d_in[3];
    const float* b1   = (const float*)d_in[4];
    const float* We1  = (const float*)d_in[5];
    const float* att1 = (const float*)d_in[6];
    // d_in[7] = bo1: cancels in BatchNorm
    const float* g1   = (const float*)d_in[8];
    const float* bt1  = (const float*)d_in[9];
    const float* W2   = (const float*)d_in[10];
    const float* b2   = (const float*)d_in[11];
    const float* We2  = (const float*)d_in[12];
    const float* att2 = (const float*)d_in[13];
    // d_in[14] = bo2: cancels in BatchNorm
    const float* g2   = (const float*)d_in[15];
    const float* bt2  = (const float*)d_in[16];
    const float* W3l  = (const float*)d_in[17];
    const float* b3l  = (const float*)d_in[18];
    const float* W3r  = (const float*)d_in[19];
    const float* b3r  = (const float*)d_in[20];
    const float* We3  = (const float*)d_in[21];
    const float* att3 = (const float*)d_in[22];
    const float* bo3  = (const float*)d_in[23];
    float* out = (float*)d_out;

    float *xl1, *acc1, *xl2, *acc2;
    __half *E1, *E2;
    double *sums1, *sumsq1, *sums2, *sumsq2;
    cudaGetSymbolAddress((void**)&xl1,  g_xl1);
    cudaGetSymbolAddress((void**)&acc1, g_acc1);
    cudaGetSymbolAddress((void**)&xl2,  g_xl2);
    cudaGetSymbolAddress((void**)&acc2, g_acc2);
    cudaGetSymbolAddress((void**)&E1,   g_E1);
    cudaGetSymbolAddress((void**)&E2,   g_E2);
    cudaGetSymbolAddress((void**)&sums1, g_sums1);
    cudaGetSymbolAddress((void**)&sumsq1, g_sumsq1);
    cudaGetSymbolAddress((void**)&sums2, g_sums2);
    cudaGetSymbolAddress((void**)&sumsq2, g_sumsq2);

    static cudaStream_t sB = nullptr, sC = nullptr;
    static cudaEvent_t evFork = nullptr, evG1 = nullptr, evEg = nullptr;
    if (sB == nullptr) {
        cudaStreamCreateWithFlags(&sB, cudaStreamNonBlocking);
        cudaStreamCreateWithFlags(&sC, cudaStreamNonBlocking);
        cudaEventCreateWithFlags(&evFork, cudaEventDisableTiming);
        cudaEventCreateWithFlags(&evG1, cudaEventDisableTiming);
        cudaEventCreateWithFlags(&evEg, cudaEventDisableTiming);
    }

    // fork: gemm1 (sB) and the tf32-mma egemm (sC) overlap prep (main)
    cudaEventRecord(evFork, 0);
    cudaStreamWaitEvent(sB, evFork, 0);
    cudaStreamWaitEvent(sC, evFork, 0);

    prep_hist_ea_kernel<<<HIST_BLKS + 512, 256>>>(ei, ea);                         // launch 1
    gemm_bias_v3<128, 256, false><<<dim3(2, (NN + 127) / 128), 256, 0, sB>>>(
        x, W1, b1, xl1, NN, nullptr, nullptr);                                     // launch 2
    cudaEventRecord(evG1, sB);
    scan1_kernel<<<NB, 256>>>();                                                   // launch 3
    egemm_mma_kernel<<<(EE + 127) / 128, 256, 0, sC>>>(ea, We1, We2, E1, E2);      // launch 4 <- profiled
    cudaEventRecord(evEg, sC);

    scan2_kernel<<<1, 256>>>();                                                    // launch 5
    scan3_kernel<<<NB, 256>>>();                                                   // launch 6
    csr_scatter_kernel<<<(ETOT + 255) / 256, 256>>>(ei, ea, We3, We1, We2, E1, E2);// launch 7

    // layer 1 attention: needs xl1 (sB) + E1 (sC) + CSR (main)
    cudaStreamWaitEvent(0, evG1, 0);
    cudaStreamWaitEvent(0, evEg, 0);
    gat_node_kernel<256><<<GAT_BLOCKS, 256>>>(xl1, E1, att1, acc1, sums1, sumsq1); // launch 8

    // layer 2
    gemm_bias_v3<256, 128, true><<<dim3(1, (NN + 127) / 128), 256>>>(
        acc1, W2, b2, xl2, NN, g1, bt1);                                           // launch 9
    gat_node_kernel<128><<<GAT_BLOCKS, 256>>>(xl2, E2, att2, acc2, sums2, sumsq2); // launch 10

    // layer 3
    lin3_kernel<<<(NN + 7) / 8, 256>>>(acc2, g2, bt2, W3l, b3l, W3r, b3r);         // launch 11
    gat3_kernel<<<(NN + 7) / 8, 256>>>(out, att3, bo3);                            // launch 12
}

// round 16
// speedup vs baseline: 1.1437x; 1.0075x over previous
#include <cuda_runtime.h>
#include <cuda_fp16.h>
#include <math.h>

#define NN 50000
#define EE 500000
#define ETOT 550000
#define FEA 16
#define NB 196   // ceil(NN/256)
#define GAT_BLOCKS 1184   // 148 SMs * 8 blocks -> one wave

// ---------------- packed f32x2 helpers (Blackwell dual-lane fp32) ----------------
__device__ __forceinline__ unsigned long long pack2(float x, float y) {
    unsigned long long r;
    asm("mov.b64 %0, {%1, %2};" : "=l"(r) : "f"(x), "f"(y));
    return r;
}
__device__ __forceinline__ void fma2(unsigned long long& d, unsigned long long a,
                                     unsigned long long b) {
    asm("fma.rn.f32x2 %0, %1, %2, %0;" : "+l"(d) : "l"(a), "l"(b));
}
__device__ __forceinline__ float2 unpack2(unsigned long long v) {
    float lo, hi;
    asm("mov.b64 {%0, %1}, %2;" : "=f"(lo), "=f"(hi) : "l"(v));
    return make_float2(lo, hi);
}
__device__ __forceinline__ unsigned to_tf32(float v) {
    unsigned r;
    asm("cvt.rna.tf32.f32 %0, %1;" : "=r"(r) : "f"(v));
    return r;
}
__device__ __forceinline__ float2 h2f(unsigned u) {
    return __half22float2(*reinterpret_cast<const __half2*>(&u));
}

// ---------------- scratch (static device globals; no allocation) ----------------
__device__ __half g_xl1[NN * 256];        // node transform layer1, fp16
__device__ float  g_acc1[NN * 256];
__device__ __half g_xl2[NN * 128];        // node transform layer2, fp16
__device__ float  g_acc2[NN * 128];
__device__ __half g_E1[(EE + 1) * 256];   // edge transform, EID order (+1 self-loop row)
__device__ __half g_E2[(EE + 1) * 128];
__device__ float  g_E3[ETOT];             // CSR order
__device__ float  g_xl3[NN];
__device__ float  g_xr3[NN];
__device__ int    g_cnt[NN];
__device__ int    g_rows[NN + 1];
__device__ int    g_cur[NN];
__device__ int    g_csrc[ETOT];
__device__ int    g_ceid[ETOT];
__device__ int    g_bsums[256];
__device__ int    g_dhist[64];
__device__ int    g_dcur[64];
__device__ int    g_nodeperm[NN];
__device__ double g_sums1[256];
__device__ double g_sumsq1[256];
__device__ double g_sums2[128];
__device__ double g_sumsq2[128];
__device__ double g_easum[FEA];
__device__ float  g_eamean[FEA];

// ---------------- prep: dst histogram + edge_attr column sums (merged) ----------------
#define HIST_BLKS 1954
__global__ void prep_hist_ea_kernel(const int* __restrict__ ei, const float* __restrict__ ea) {
    if (blockIdx.x < HIST_BLKS) {
        int e = blockIdx.x * 256 + threadIdx.x;
        if (e < EE) atomicAdd(&g_cnt[__ldcs(&ei[EE + e])], 1);
    } else {
        long tid = (long)(blockIdx.x - HIST_BLKS) * 256 + threadIdx.x;
        long stride = 512L * 256;
        int k = (int)(tid & 15);
        double sv = 0.0;
        for (long i = tid; i < (long)EE * FEA; i += stride) sv += (double)__ldcs(&ea[i]);
        atomicAdd(&g_easum[k], sv);
    }
}

// ---------------- CSR scan chain (+ degree histogram for node sort) ----------------
__global__ void scan1_kernel() {
    __shared__ int s[256];
    int t = threadIdx.x;
    int i = blockIdx.x * 256 + t;
    int v = 0;
    if (i < NN) {
        v = g_cnt[i] + 1;   // +1 self loop
        g_cnt[i] = v;
        atomicAdd(&g_dhist[min(v, 63)], 1);
    }
    s[t] = v;
    __syncthreads();
#pragma unroll
    for (int off = 1; off < 256; off <<= 1) {
        int x = (t >= off) ? s[t - off] : 0;
        __syncthreads();
        s[t] += x;
        __syncthreads();
    }
    if (i < NN) g_rows[i] = s[t];
    if (t == 255) g_bsums[blockIdx.x] = s[255];
}
__global__ void scan2_kernel() {
    __shared__ int s[256];
    int t = threadIdx.x;
    if (t < FEA) {
        g_eamean[t] = (float)(g_easum[t] / (double)EE);
        g_easum[t] = 0.0;
    }
    g_sums1[t] = 0.0; g_sumsq1[t] = 0.0;
    if (t < 128) { g_sums2[t] = 0.0; g_sumsq2[t] = 0.0; }
    int v = (t < NB) ? g_bsums[t] : 0;
    s[t] = v;
    __syncthreads();
#pragma unroll
    for (int off = 1; off < 256; off <<= 1) {
        int x = (t >= off) ? s[t - off] : 0;
        __syncthreads();
        s[t] += x;
        __syncthreads();
    }
    g_bsums[t] = s[t] - v;
    __syncthreads();
    int dv = (t < 64) ? g_dhist[t] : 0;
    s[t] = dv;
    __syncthreads();
#pragma unroll
    for (int off = 1; off < 64; off <<= 1) {
        int x = (t >= off) ? s[t - off] : 0;
        __syncthreads();
        s[t] += x;
        __syncthreads();
    }
    if (t < 64) g_dcur[t] = NN - s[t];
}
__global__ void scan3_kernel() {
    int i = blockIdx.x * blockDim.x + threadIdx.x;
    if (i < NN) {
        int deg = g_cnt[i];
        int r = g_rows[i] - deg + g_bsums[i >> 8];
        g_rows[i] = r;
        g_cur[i] = r;
        int pos = atomicAdd(&g_dcur[min(deg, 63)], 1);
        g_nodeperm[pos] = i;
    }
    if (i == 0) g_rows[NN] = ETOT;
}
// CSR scatter + E3 + self-loop rows of E1/E2; resets g_cnt/g_dhist
__global__ void csr_scatter_kernel(const int* __restrict__ ei, const float* __restrict__ ea,
                                   const float* __restrict__ We3,
                                   const float* __restrict__ We1, const float* __restrict__ We2,
                                   __half* __restrict__ E1, __half* __restrict__ E2) {
    __shared__ float We_s[FEA];
    __shared__ float mean_s[FEA];
    __shared__ float mdot;
    if (threadIdx.x < FEA) {
        We_s[threadIdx.x] = We3[threadIdx.x];
        mean_s[threadIdx.x] = g_eamean[threadIdx.x];
    }
    __syncthreads();
    if (threadIdx.x == 0) {
        float s = 0.f;
#pragma unroll
        for (int k = 0; k < FEA; k++) s += mean_s[k] * We_s[k];
        mdot = s;
    }
    __syncthreads();
    if (blockIdx.x == 0) {
        int c = threadIdx.x;
        {
            float s = 0.f;
#pragma unroll
            for (int k = 0; k < FEA; k++) s += mean_s[k] * We1[k * 256 + c];
            E1[(size_t)EE * 256 + c] = __float2half_rn(s);
        }
        if (c < 128) {
            float s = 0.f;
#pragma unroll
            for (int k = 0; k < FEA; k++) s += mean_s[k] * We2[k * 128 + c];
            E2[(size_t)EE * 128 + c] = __float2half_rn(s);
        }
    }
    int e = blockIdx.x * blockDim.x + threadIdx.x;
    if (e >= ETOT) return;
    if (e < NN) g_cnt[e] = 0;
    if (e < 64) g_dhist[e] = 0;
    int s, d, eid;
    float dot;
    if (e < EE) {
        s = ei[e]; d = ei[EE + e]; eid = e;
        dot = 0.f;
        const float* eap = ea + (size_t)e * FEA;
#pragma unroll
        for (int k = 0; k < FEA; k++) dot += __ldcs(&eap[k]) * We_s[k];
    } else {
        s = e - EE; d = s; eid = EE;
        dot = mdot;
    }
    int pos = atomicAdd(&g_cur[d], 1);
    g_csrc[pos] = s;
    g_ceid[pos] = eid;
    g_E3[pos] = dot;
}

// ---------------- tensor-core egemm: tf32 mma, B fragments from global, staged stores ---
__global__ void __launch_bounds__(256)
egemm_mma_kernel(const float* __restrict__ ea,
                 const float* __restrict__ We1, const float* __restrict__ We2,
                 __half* __restrict__ E1, __half* __restrict__ E2) {
    __shared__ unsigned sA[128 * 17];      // [row][k] tf32, padded
    __shared__ __half sStage[16 * 392];    // 16 rows x 384 cols, padded to 392
    int tid = threadIdx.x;
    int warp = tid >> 5, lane = tid & 31;
    int g = lane >> 2, tg = lane & 3;
    int e0 = blockIdx.x * 128;

    {
        int row = tid >> 1, q = tid & 1;
        int e = e0 + row;
        float4 v0 = make_float4(0.f, 0.f, 0.f, 0.f), v1 = v0;
        if (e < EE) {
            const float4* p = reinterpret_cast<const float4*>(ea + (size_t)e * 16 + q * 8);
            v0 = __ldcs(&p[0]);
            v1 = __ldcs(&p[1]);
        }
        unsigned* dst = &sA[row * 17 + q * 8];
        dst[0] = to_tf32(v0.x); dst[1] = to_tf32(v0.y);
        dst[2] = to_tf32(v0.z); dst[3] = to_tf32(v0.w);
        dst[4] = to_tf32(v1.x); dst[5] = to_tf32(v1.y);
        dst[6] = to_tf32(v1.z); dst[7] = to_tf32(v1.w);
    }

    unsigned bf[6][2][2];
    int cbs[6];
#pragma unroll
    for (int j = 0; j < 6; j++) {
        int cb = (warp + j * 8) * 8;
        cbs[j] = cb;
        int col = cb + g;
        const float* Bp;
        int ldb;
        if (cb < 256) { Bp = We1; ldb = 256; }
        else          { Bp = We2; ldb = 128; col -= 256; }
        bf[j][0][0] = to_tf32(__ldg(&Bp[(size_t)tg * ldb + col]));
        bf[j][0][1] = to_tf32(__ldg(&Bp[(size_t)(tg + 4) * ldb + col]));
        bf[j][1][0] = to_tf32(__ldg(&Bp[(size_t)(8 + tg) * ldb + col]));
        bf[j][1][1] = to_tf32(__ldg(&Bp[(size_t)(12 + tg) * ldb + col]));
    }
    __syncthreads();

#pragma unroll
    for (int eg = 0; eg < 8; eg++) {
        int r0 = eg * 16;
        const unsigned* apg  = &sA[(r0 + g) * 17];
        const unsigned* apg8 = &sA[(r0 + g + 8) * 17];
        unsigned a00 = apg[tg],      a01 = apg8[tg],      a02 = apg[tg + 4],      a03 = apg8[tg + 4];
        unsigned a10 = apg[8 + tg],  a11 = apg8[8 + tg],  a12 = apg[8 + tg + 4],  a13 = apg8[8 + tg + 4];
#pragma unroll
        for (int j = 0; j < 6; j++) {
            float c0 = 0.f, c1 = 0.f, c2 = 0.f, c3 = 0.f;
            asm volatile(
                "mma.sync.aligned.m16n8k8.row.col.f32.tf32.tf32.f32 "
                "{%0,%1,%2,%3}, {%4,%5,%6,%7}, {%8,%9}, {%0,%1,%2,%3};"
                : "+f"(c0), "+f"(c1), "+f"(c2), "+f"(c3)
                : "r"(a00), "r"(a01), "r"(a02), "r"(a03),
                  "r"(bf[j][0][0]), "r"(bf[j][0][1]));
            asm volatile(
                "mma.sync.aligned.m16n8k8.row.col.f32.tf32.tf32.f32 "
                "{%0,%1,%2,%3}, {%4,%5,%6,%7}, {%8,%9}, {%0,%1,%2,%3};"
                : "+f"(c0), "+f"(c1), "+f"(c2), "+f"(c3)
                : "r"(a10), "r"(a11), "r"(a12), "r"(a13),
                  "r"(bf[j][1][0]), "r"(bf[j][1][1]));
            __half2 h01 = __floats2half2_rn(c0, c1);
            __half2 h23 = __floats2half2_rn(c2, c3);
            int cc = cbs[j] + 2 * tg;
            *reinterpret_cast<__half2*>(&sStage[g * 392 + cc]) = h01;
            *reinterpret_cast<__half2*>(&sStage[(g + 8) * 392 + cc]) = h23;
        }
        __syncthreads();
        {
            int it = tid;
#pragma unroll
            for (int rep = 0; rep < 2; rep++) {
                int row = it >> 5, c16 = it & 31;
                int ge = e0 + r0 + row;
                if (ge < EE) {
                    uint4 v = *reinterpret_cast<const uint4*>(&sStage[row * 392 + c16 * 8]);
                    __stcs(reinterpret_cast<uint4*>(E1 + (size_t)ge * 256 + c16 * 8), v);
                }
                it += 256;
            }
            int row = tid >> 4, c16 = tid & 15;
            int ge = e0 + r0 + row;
            if (ge < EE) {
                uint4 v = *reinterpret_cast<const uint4*>(&sStage[row * 392 + 256 + c16 * 8]);
                __stcs(reinterpret_cast<uint4*>(E2 + (size_t)ge * 128 + c16 * 8), v);
            }
        }
        __syncthreads();
    }
}

// ---------------- SGEMM 128x128 tile, 8x8/thread, f32x2 packed, fp16 or fp32 output ----
template <int K, int M, bool FUSE_BN, typename OutT>
__global__ void __launch_bounds__(256, 2)
gemm_bias_v3(const float* __restrict__ A, const float* __restrict__ B,
             const float* __restrict__ bias, OutT* __restrict__ C, int n,
             const float* __restrict__ gam, const float* __restrict__ bet) {
    __shared__ float As[2][16][132];
    __shared__ float Bs[2][16][132];
    __shared__ float sSc[FUSE_BN ? K : 1];
    __shared__ float sSh[FUSE_BN ? K : 1];
    constexpr int KT = K / 16;
    int tid = threadIdx.x;
    int tx = tid & 15, ty = tid >> 4;
    int row0 = blockIdx.y * 128, col0 = blockIdx.x * 128;

    if (FUSE_BN) {
        for (int j = tid; j < K; j += 256) {
            double mu = g_sums1[j] / (double)NN;
            double var = g_sumsq1[j] / (double)NN - mu * mu;
            float sc = gam[j] * rsqrtf((float)var + 1e-5f);
            sSc[j] = sc;
            sSh[j] = bet[j] - sc * (float)mu;
        }
        __syncthreads();
    }

    int a_r = tid >> 2, a_q = tid & 3;
    int b_kr = tid >> 5, b_cq = tid & 31;

    float4 aR[2], bR[2];
    auto bnf = [&](float a, int k) -> float {
        if (!FUSE_BN) return a;
        float y = sSc[k] * a + sSh[k];
        return y > 0.f ? y : (__expf(y) - 1.f);
    };
    auto loadG = [&](int kk) {
#pragma unroll
        for (int u = 0; u < 2; u++) {
            int grow = row0 + a_r + u * 64;
            aR[u] = (grow < n) ? reinterpret_cast<const float4*>(A + (size_t)grow * K + kk)[a_q]
                               : make_float4(0.f, 0.f, 0.f, 0.f);
            bR[u] = reinterpret_cast<const float4*>(B + (size_t)(kk + b_kr + u * 8) * M + col0)[b_cq];
        }
    };
    auto storeS = [&](int buf, int kk) {
#pragma unroll
        for (int u = 0; u < 2; u++) {
            int r = a_r + u * 64;
            As[buf][a_q * 4 + 0][r] = bnf(aR[u].x, kk + a_q * 4 + 0);
            As[buf][a_q * 4 + 1][r] = bnf(aR[u].y, kk + a_q * 4 + 1);
            As[buf][a_q * 4 + 2][r] = bnf(aR[u].z, kk + a_q * 4 + 2);
            As[buf][a_q * 4 + 3][r] = bnf(aR[u].w, kk + a_q * 4 + 3);
            reinterpret_cast<float4*>(&Bs[buf][b_kr + u * 8][0])[b_cq] = bR[u];
        }
    };

    unsigned long long acc[8][4];
#pragma unroll
    for (int i = 0; i < 8; i++)
#pragma unroll
        for (int j = 0; j < 4; j++) acc[i][j] = pack2(0.f, 0.f);

    loadG(0);
    storeS(0, 0);
    __syncthreads();
#pragma unroll
    for (int kt = 0; kt < KT; kt++) {
        if (kt + 1 < KT) loadG((kt + 1) * 16);
        int cur = kt & 1;
#pragma unroll
        for (int k = 0; k < 16; k++) {
            float a[8];
            float4 b4[2];
            *reinterpret_cast<float4*>(a)     = *reinterpret_cast<const float4*>(&As[cur][k][ty * 8]);
            *reinterpret_cast<float4*>(a + 4) = *reinterpret_cast<const float4*>(&As[cur][k][ty * 8 + 4]);
            b4[0] = *reinterpret_cast<const float4*>(&Bs[cur][k][tx * 8]);
            b4[1] = *reinterpret_cast<const float4*>(&Bs[cur][k][tx * 8 + 4]);
            const unsigned long long* bv = reinterpret_cast<const unsigned long long*>(b4);
#pragma unroll
            for (int i = 0; i < 8; i++) {
                unsigned long long av = pack2(a[i], a[i]);
#pragma unroll
                for (int j = 0; j < 4; j++) fma2(acc[i][j], av, bv[j]);
            }
        }
        if (kt + 1 < KT) {
            storeS((kt + 1) & 1, (kt + 1) * 16);
            __syncthreads();
        }
    }
    float4 bv0 = reinterpret_cast<const float4*>(bias + col0 + tx * 8)[0];
    float4 bv1 = reinterpret_cast<const float4*>(bias + col0 + tx * 8)[1];
    float bb[8] = {bv0.x, bv0.y, bv0.z, bv0.w, bv1.x, bv1.y, bv1.z, bv1.w};
#pragma unroll
    for (int i = 0; i < 8; i++) {
        int r = row0 + ty * 8 + i;
        if (r < n) {
            float w[8];
#pragma unroll
            for (int j = 0; j < 4; j++) {
                float2 p = unpack2(acc[i][j]);
                w[j * 2] = p.x + bb[j * 2];
                w[j * 2 + 1] = p.y + bb[j * 2 + 1];
            }
            if (sizeof(OutT) == 2) {
                __half2 h0 = __floats2half2_rn(w[0], w[1]);
                __half2 h1 = __floats2half2_rn(w[2], w[3]);
                __half2 h2 = __floats2half2_rn(w[4], w[5]);
                __half2 h3 = __floats2half2_rn(w[6], w[7]);
                uint4 v;
                v.x = *reinterpret_cast<unsigned*>(&h0);
                v.y = *reinterpret_cast<unsigned*>(&h1);
                v.z = *reinterpret_cast<unsigned*>(&h2);
                v.w = *reinterpret_cast<unsigned*>(&h3);
                *reinterpret_cast<uint4*>((__half*)C + (size_t)r * M + col0 + tx * 8) = v;
            } else {
                float4* cp = reinterpret_cast<float4*>((float*)C + (size_t)r * M + col0 + tx * 8);
                cp[0] = make_float4(w[0], w[1], w[2], w[3]);
                cp[1] = make_float4(w[4], w[5], w[6], w[7]);
            }
        }
    }
}

// ---------------- warp-persistent GATv2 attention (fp16 xl + E) + register BN ----------
template <int D>
__global__ void __launch_bounds__(256)
gat_node_kernel(const __half* __restrict__ xl, const __half* __restrict__ E,
                const float* __restrict__ att, float* __restrict__ outx,
                double* __restrict__ sums, double* __restrict__ sumsq) {
    constexpr int CPL = D / 32;       // 8 (D=256) or 4 (D=128)
    constexpr int NC4 = CPL / 4;      // 2 or 1
    __shared__ float bsum[8][D];
    __shared__ float bsq[8][D];
    int w = threadIdx.x >> 5;
    int lane = threadIdx.x & 31;

    const float4* at4 = reinterpret_cast<const float4*>(att);
    float4 attv[NC4];
    float fsum[CPL], fsq[CPL];
#pragma unroll
    for (int v = 0; v < NC4; v++) attv[v] = at4[lane * NC4 + v];
#pragma unroll
    for (int c = 0; c < CPL; c++) { fsum[c] = 0.f; fsq[c] = 0.f; }

    // one 16B (or 8B) load covers all CPL fp16 channels of a row for this lane
    auto load_row = [&](const __half* base, uint4& r) {
        if (NC4 == 2) {
            r = *(reinterpret_cast<const uint4*>(base) + lane);
        } else {
            uint2 t = *(reinterpret_cast<const uint2*>(base) + lane);
            r.x = t.x; r.y = t.y; r.z = 0u; r.w = 0u;
        }
    };
    auto load_er = [&](int eid, uint4& er) {
        if (NC4 == 2) {
            er = __ldcs(reinterpret_cast<const uint4*>(E + (size_t)eid * D) + lane);
        } else {
            uint2 t = __ldcs(reinterpret_cast<const uint2*>(E + (size_t)eid * D) + lane);
            er.x = t.x; er.y = t.y; er.z = 0u; er.w = 0u;
        }
    };

    for (int g = blockIdx.x * 8 + w; g < NN; g += GAT_BLOCKS * 8) {
        int node = g_nodeperm[g];
        int beg = g_rows[node], end = g_rows[node + 1];
        uint4 xdr;
        load_row(xl + (size_t)node * D, xdr);
        float4 xdv[NC4], accv[NC4];
        float den = 0.f;
#pragma unroll
        for (int v = 0; v < NC4; v++) {
            float2 d01 = h2f(v == 0 ? xdr.x : xdr.z);
            float2 d23 = h2f(v == 0 ? xdr.y : xdr.w);
            xdv[v] = make_float4(d01.x, d01.y, d23.x, d23.y);
            accv[v] = make_float4(0.f, 0.f, 0.f, 0.f);
        }

        auto edge_compute = [&](const uint4& xs, const uint4& er) {
            float4 xsf[NC4];
            float p = 0.f;
#pragma unroll
            for (int v = 0; v < NC4; v++) {
                float2 x01 = h2f(v == 0 ? xs.x : xs.z);
                float2 x23 = h2f(v == 0 ? xs.y : xs.w);
                xsf[v] = make_float4(x01.x, x01.y, x23.x, x23.y);
                float2 e01 = h2f(v == 0 ? er.x : er.z);
                float2 e23 = h2f(v == 0 ? er.y : er.w);
                float m0 = xsf[v].x + xdv[v].x + e01.x;
                float m1 = xsf[v].y + xdv[v].y + e01.y;
                float m2 = xsf[v].z + xdv[v].z + e23.x;
                float m3 = xsf[v].w + xdv[v].w + e23.y;
                float l0 = m0 > 0.f ? m0 : 0.2f * m0;
                float l1 = m1 > 0.f ? m1 : 0.2f * m1;
                float l2 = m2 > 0.f ? m2 : 0.2f * m2;
                float l3 = m3 > 0.f ? m3 : 0.2f * m3;
                p += l0 * attv[v].x + l1 * attv[v].y + l2 * attv[v].z + l3 * attv[v].w;
            }
            p += __shfl_xor_sync(0xffffffffu, p, 1);
            p += __shfl_xor_sync(0xffffffffu, p, 2);
            float ev = __expf(p);
            den += ev;
#pragma unroll
            for (int v = 0; v < NC4; v++) {
                accv[v].x += ev * xsf[v].x;
                accv[v].y += ev * xsf[v].y;
                accv[v].z += ev * xsf[v].z;
                accv[v].w += ev * xsf[v].w;
            }
        };

        int i = beg;
        for (; i + 4 <= end; i += 4) {
            int s0 = g_csrc[i], s1 = g_csrc[i + 1], s2 = g_csrc[i + 2], s3 = g_csrc[i + 3];
            int e0 = g_ceid[i], e1 = g_ceid[i + 1], e2 = g_ceid[i + 2], e3 = g_ceid[i + 3];
            uint4 xs0, xs1, xs2, xs3, er0, er1, er2, er3;
            load_row(xl + (size_t)s0 * D, xs0);
            load_row(xl + (size_t)s1 * D, xs1);
            load_row(xl + (size_t)s2 * D, xs2);
            load_row(xl + (size_t)s3 * D, xs3);
            load_er(e0, er0); load_er(e1, er1); load_er(e2, er2); load_er(e3, er3);
            edge_compute(xs0, er0);
            edge_compute(xs1, er1);
            edge_compute(xs2, er2);
            edge_compute(xs3, er3);
        }
        for (; i < end; i++) {
            int s0 = g_csrc[i];
            int e0 = g_ceid[i];
            uint4 xs0, er0;
            load_row(xl + (size_t)s0 * D, xs0);
            load_er(e0, er0);
            edge_compute(xs0, er0);
        }

        float4* o4 = reinterpret_cast<float4*>(outx + (size_t)node * D);
        float inv = 1.f / (den + 1e-16f);
#pragma unroll
        for (int v = 0; v < NC4; v++) {
            float4 o = make_float4(accv[v].x * inv, accv[v].y * inv,
                                   accv[v].z * inv, accv[v].w * inv);
            o4[lane * NC4 + v] = o;
            fsum[v * 4 + 0] += o.x; fsq[v * 4 + 0] += o.x * o.x;
            fsum[v * 4 + 1] += o.y; fsq[v * 4 + 1] += o.y * o.y;
            fsum[v * 4 + 2] += o.z; fsq[v * 4 + 2] += o.z * o.z;
            fsum[v * 4 + 3] += o.w; fsq[v * 4 + 3] += o.w * o.w;
        }
    }

#pragma unroll
    for (int c = 0; c < CPL; c++) {
        bsum[w][lane * CPL + c] = fsum[c];
        bsq[w][lane * CPL + c] = fsq[c];
    }
    __syncthreads();
    int c = threadIdx.x;
    if (c < D) {
        float s = 0.f, s2 = 0.f;
#pragma unroll
        for (int u = 0; u < 8; u++) { s += bsum[u][c]; s2 += bsq[u][c]; }
        atomicAdd(&sums[c], (double)s);
        atomicAdd(&sumsq[c], (double)s2);
    }
}

// ---------------- layer 3: BN+ELU fused into the two scalar transforms ----------------
__global__ void lin3_kernel(const float* __restrict__ h2,
                            const float* __restrict__ gam, const float* __restrict__ bet,
                            const float* __restrict__ W3l, const float* __restrict__ b3l,
                            const float* __restrict__ W3r, const float* __restrict__ b3r) {
    __shared__ float sSc[128], sSh[128];
    int tid = threadIdx.x;
    if (tid < 128) {
        double mu = g_sums2[tid] / (double)NN;
        double var = g_sumsq2[tid] / (double)NN - mu * mu;
        float sc = gam[tid] * rsqrtf((float)var + 1e-5f);
        sSc[tid] = sc;
        sSh[tid] = bet[tid] - sc * (float)mu;
    }
    __syncthreads();
    int w = blockIdx.x * 8 + (tid >> 5);
    if (w >= NN) return;
    int lane = tid & 31;
    const float* row = h2 + (size_t)w * 128;
    float sl = 0.f, sr = 0.f;
#pragma unroll
    for (int q = 0; q < 4; q++) {
        int j = q * 32 + lane;
        float v = sSc[j] * row[j] + sSh[j];
        v = v > 0.f ? v : (__expf(v) - 1.f);
        sl += v * W3l[j];
        sr += v * W3r[j];
    }
#pragma unroll
    for (int off = 16; off >= 1; off >>= 1) {
        sl += __shfl_down_sync(0xffffffffu, sl, off);
        sr += __shfl_down_sync(0xffffffffu, sr, off);
    }
    if (lane == 0) {
        g_xl3[w] = sl + b3l[0];
        g_xr3[w] = sr + b3r[0];
    }
}

__global__ void gat3_kernel(float* __restrict__ out, const float* __restrict__ att3,
                            const float* __restrict__ bo3) {
    int node = blockIdx.x * 8 + (threadIdx.x >> 5);
    if (node >= NN) return;
    int lane = threadIdx.x & 31;
    int beg = g_rows[node], end = g_rows[node + 1];
    float xr = g_xr3[node];
    float a3 = att3[0];
    float num = 0.f, den = 0.f;
    for (int i = beg + lane; i < end; i += 32) {
        int s = g_csrc[i];
        float xls = g_xl3[s];
        float m = xls + xr + g_E3[i];
        float lg = (m > 0.f ? m : 0.2f * m) * a3;
        float ev = __expf(lg);
        den += ev;
        num += ev * xls;
    }
#pragma unroll
    for (int off = 16; off >= 1; off >>= 1) {
        num += __shfl_down_sync(0xffffffffu, num, off);
        den += __shfl_down_sync(0xffffffffu, den, off);
    }
    if (lane == 0) out[node] = num / (den + 1e-16f) + bo3[0];
}

// ---------------- host launch ----------------
extern "C" void kernel_launch(void* const* d_in, const int* in_sizes, int n_in,
                              void* d_out, int out_size) {
    const float* x    = (const float*)d_in[0];
    const int*   ei   = (const int*)d_in[1];
    const float* ea   = (const float*)d_in[2];
    const float* W1   = (const float*)d_in[3];
    const float* b1   = (const float*)d_in[4];
    const float* We1  = (const float*)d_in[5];
    const float* att1 = (const float*)d_in[6];
    // d_in[7] = bo1: cancels in BatchNorm
    const float* g1   = (const float*)d_in[8];
    const float* bt1  = (const float*)d_in[9];
    const float* W2   = (const float*)d_in[10];
    const float* b2   = (const float*)d_in[11];
    const float* We2  = (const float*)d_in[12];
    const float* att2 = (const float*)d_in[13];
    // d_in[14] = bo2: cancels in BatchNorm
    const float* g2   = (const float*)d_in[15];
    const float* bt2  = (const float*)d_in[16];
    const float* W3l  = (const float*)d_in[17];
    const float* b3l  = (const float*)d_in[18];
    const float* W3r  = (const float*)d_in[19];
    const float* b3r  = (const float*)d_in[20];
    const float* We3  = (const float*)d_in[21];
    const float* att3 = (const float*)d_in[22];
    const float* bo3  = (const float*)d_in[23];
    float* out = (float*)d_out;

    __half *xl1, *xl2, *E1, *E2;
    float *acc1, *acc2;
    double *sums1, *sumsq1, *sums2, *sumsq2;
    cudaGetSymbolAddress((void**)&xl1,  g_xl1);
    cudaGetSymbolAddress((void**)&acc1, g_acc1);
    cudaGetSymbolAddress((void**)&xl2,  g_xl2);
    cudaGetSymbolAddress((void**)&acc2, g_acc2);
    cudaGetSymbolAddress((void**)&E1,   g_E1);
    cudaGetSymbolAddress((void**)&E2,   g_E2);
    cudaGetSymbolAddress((void**)&sums1, g_sums1);
    cudaGetSymbolAddress((void**)&sumsq1, g_sumsq1);
    cudaGetSymbolAddress((void**)&sums2, g_sums2);
    cudaGetSymbolAddress((void**)&sumsq2, g_sumsq2);

    static cudaStream_t sB = nullptr, sC = nullptr;
    static cudaEvent_t evFork = nullptr, evG1 = nullptr, evEg = nullptr;
    if (sB == nullptr) {
        cudaStreamCreateWithFlags(&sB, cudaStreamNonBlocking);
        cudaStreamCreateWithFlags(&sC, cudaStreamNonBlocking);
        cudaEventCreateWithFlags(&evFork, cudaEventDisableTiming);
        cudaEventCreateWithFlags(&evG1, cudaEventDisableTiming);
        cudaEventCreateWithFlags(&evEg, cudaEventDisableTiming);
    }

    // fork: gemm1 (sB) and the tf32-mma egemm (sC) overlap prep (main)
    cudaEventRecord(evFork, 0);
    cudaStreamWaitEvent(sB, evFork, 0);
    cudaStreamWaitEvent(sC, evFork, 0);

    prep_hist_ea_kernel<<<HIST_BLKS + 512, 256>>>(ei, ea);                         // launch 1
    gemm_bias_v3<128, 256, false, __half><<<dim3(2, (NN + 127) / 128), 256, 0, sB>>>(
        x, W1, b1, xl1, NN, nullptr, nullptr);                                     // launch 2
    cudaEventRecord(evG1, sB);
    scan1_kernel<<<NB, 256>>>();                                                   // launch 3
    egemm_mma_kernel<<<(EE + 127) / 128, 256, 0, sC>>>(ea, We1, We2, E1, E2);      // launch 4 <- profiled
    cudaEventRecord(evEg, sC);

    scan2_kernel<<<1, 256>>>();                                                    // launch 5
    scan3_kernel<<<NB, 256>>>();                                                   // launch 6
    csr_scatter_kernel<<<(ETOT + 255) / 256, 256>>>(ei, ea, We3, We1, We2, E1, E2);// launch 7

    // layer 1 attention: needs xl1 (sB) + E1 (sC) + CSR (main)
    cudaStreamWaitEvent(0, evG1, 0);
    cudaStreamWaitEvent(0, evEg, 0);
    gat_node_kernel<256><<<GAT_BLOCKS, 256>>>(xl1, E1, att1, acc1, sums1, sumsq1); // launch 8

    // layer 2
    gemm_bias_v3<256, 128, true, __half><<<dim3(1, (NN + 127) / 128), 256>>>(
        acc1, W2, b2, xl2, NN, g1, bt1);                                           // launch 9
    gat_node_kernel<128><<<GAT_BLOCKS, 256>>>(xl2, E2, att2, acc2, sums2, sumsq2); // launch 10

    // layer 3
    lin3_kernel<<<(NN + 7) / 8, 256>>>(acc2, g2, bt2, W3l, b3l, W3r, b3r);         // launch 11
    gat3_kernel<<<(NN + 7) / 8, 256>>>(out, att3, bo3);                            // launch 12
}